// round 5
// baseline (speedup 1.0000x reference)
#include <cuda_runtime.h>
#include <math.h>

#define N_NODES 20000
#define N_EDGES 320000
#define N_GRAPHS 64
#define DIM 128

// ---------------- scratch (device globals; no allocation allowed) ----------
__device__ float g_feat[N_NODES * 768];   // per-layer fc output [N, H*D]
__device__ float g_x1[N_NODES * 512];     // layer0 output (tf32-rounded)
__device__ float g_x2[N_NODES * 512];     // layer1 output (tf32-rounded)
__device__ float g_res[N_NODES * 768];    // layer2 linear residual
__device__ float g_x3[N_NODES * 768];     // layer2 output; front also holds rounded h
__device__ float g_el[N_NODES * 6];
__device__ float g_er[N_NODES * 6];
__device__ float g_alpha[N_EDGES * 6];    // normalized attn weights (sorted order)
__device__ int   g_counts[N_NODES];
__device__ int   g_off[N_NODES + 1];
__device__ int   g_cursor[N_NODES];
__device__ int   g_ssrc[N_EDGES];         // src node per sorted edge slot
__device__ float g_gsum[N_GRAPHS * DIM];
__device__ int   g_gcnt[N_GRAPHS];
__device__ float g_wr[1114112];           // rounded weights: W0|W1|W2|resW2

__device__ __forceinline__ float f2tf32(float x) {
    unsigned r;
    asm("cvt.rna.tf32.f32 %0, %1;" : "=r"(r) : "f"(x));
    return __uint_as_float(r);
}

// ---------------- small utility kernels ------------------------------------
__global__ void k_zero_int(int* p, int n) {
    int i = blockIdx.x * blockDim.x + threadIdx.x;
    if (i < n) p[i] = 0;
}
__global__ void k_zero_float(float* p, int n) {
    int i = blockIdx.x * blockDim.x + threadIdx.x;
    if (i < n) p[i] = 0.f;
}
__global__ void k_round4(const float4* __restrict__ in, float4* __restrict__ out, int n4) {
    int i = blockIdx.x * blockDim.x + threadIdx.x;
    if (i < n4) {
        float4 v = in[i];
        v.x = f2tf32(v.x); v.y = f2tf32(v.y);
        v.z = f2tf32(v.z); v.w = f2tf32(v.w);
        out[i] = v;
    }
}
__global__ void k_count(const int* __restrict__ dst, int* counts, int E) {
    int e = blockIdx.x * blockDim.x + threadIdx.x;
    if (e < E) atomicAdd(&counts[dst[e]], 1);
}

// single-block shuffle scan: off[0]=0, off[i+1]=off[i]+counts[i]; cursor[i]=off[i]
__global__ void k_scan(const int* __restrict__ counts, int* off, int* cursor, int n) {
    __shared__ int warp_sums[32];
    __shared__ int carry_s;
    int t = threadIdx.x, lane = t & 31, w = t >> 5;
    if (t == 0) { carry_s = 0; off[0] = 0; }
    __syncthreads();
    for (int base = 0; base < n; base += 1024) {
        int v = (base + t < n) ? counts[base + t] : 0;
        int x = v;
        #pragma unroll
        for (int o = 1; o < 32; o <<= 1) {
            int y = __shfl_up_sync(0xffffffffu, x, o);
            if (lane >= o) x += y;
        }
        if (lane == 31) warp_sums[w] = x;
        __syncthreads();
        if (w == 0) {
            int s = warp_sums[lane];
            #pragma unroll
            for (int o = 1; o < 32; o <<= 1) {
                int y = __shfl_up_sync(0xffffffffu, s, o);
                if (lane >= o) s += y;
            }
            warp_sums[lane] = s;
        }
        __syncthreads();
        int pre = (w > 0) ? warp_sums[w - 1] : 0;
        int incl = x + pre + carry_s;
        if (base + t < n) {
            off[base + t + 1] = incl;
            cursor[base + t] = incl - v;
        }
        __syncthreads();
        if (t == 0) carry_s += warp_sums[31];
        __syncthreads();
    }
}
__global__ void k_fill(const int* __restrict__ dst, const int* __restrict__ src,
                       int* cursor, int* ssrc, int E) {
    int e = blockIdx.x * blockDim.x + threadIdx.x;
    if (e < E) {
        int pos = atomicAdd(&cursor[dst[e]], 1);
        ssrc[pos] = src[e];
    }
}

// ---------------- TF32 tensor-core GEMM: C[N,M]=A[N,K]@B[K,M] row-major -----
// Inputs MUST be pre-rounded to tf32. 128x128x32 tile, 3-stage cp.async,
// ldmatrix A fragments, zero cvt in mainloop.
#define GBM 128
#define GBN 128
#define GBK 32
#define AP 36    // A smem pitch (floats)
#define BP 136   // B smem pitch (floats)
#define AS_FLOATS (GBM * AP)                 // 4608
#define BS_FLOATS (GBK * BP)                 // 4352
#define STAGE_FLOATS (AS_FLOATS + BS_FLOATS) // 8960
#define NSTAGE 3
#define GEMM_SMEM (NSTAGE * STAGE_FLOATS * 4)  // 107520 bytes

__global__ __launch_bounds__(256)
void k_tf32gemm(const float* __restrict__ A, const float* __restrict__ B,
                float* __restrict__ C, int N, int K, int M) {
    extern __shared__ float sm[];
    int t = threadIdx.x;
    int warp = t >> 5, lane = t & 31;
    int grp = lane >> 2;   // 0..7
    int qr  = lane & 3;    // 0..3
    int wm = (warp >> 2) * 64;   // 2x4 warp grid -> 64x32 warp tiles
    int wn = (warp & 3) * 32;
    int rb = blockIdx.y * GBM;
    int cb = blockIdx.x * GBN;

    float acc[4][4][4];
    #pragma unroll
    for (int i = 0; i < 4; i++)
        #pragma unroll
        for (int j = 0; j < 4; j++)
            #pragma unroll
            for (int k = 0; k < 4; k++) acc[i][j][k] = 0.f;

    unsigned smbase = (unsigned)__cvta_generic_to_shared(sm);
    unsigned asb[NSTAGE], bsb[NSTAGE];
    #pragma unroll
    for (int s = 0; s < NSTAGE; s++) {
        asb[s] = smbase + (unsigned)(s * STAGE_FLOATS) * 4u;
        bsb[s] = asb[s] + AS_FLOATS * 4u;
    }

    int aR = t >> 3;          // 0..31 (+32j)
    int aC = (t & 7) * 4;
    int bR = t >> 5;          // 0..7  (+8j)
    int bC = (t & 31) * 4;

    int sub = lane >> 3, li = lane & 7;
    int lrow = wm + ((sub & 1) << 3) + li;
    int lcol = (sub & 2) ? 4 : 0;

    int NIT = K / GBK;

    #define ISSUE_STAGE(s, k0)                                                      \
    {                                                                               \
        unsigned as_ = asb[s], bs_ = bsb[s];                                        \
        _Pragma("unroll")                                                           \
        for (int j = 0; j < 4; j++) {                                               \
            int r = aR + 32 * j;                                                    \
            int gr = rb + r;                                                        \
            int sz = (gr < N) ? 16 : 0;                                             \
            const float* g = A + (size_t)(gr < N ? gr : 0) * K + (k0) + aC;         \
            unsigned d = as_ + (unsigned)(r * AP + aC) * 4u;                        \
            asm volatile("cp.async.cg.shared.global [%0], [%1], 16, %2;\n"          \
                         :: "r"(d), "l"(g), "r"(sz));                               \
        }                                                                           \
        _Pragma("unroll")                                                           \
        for (int j = 0; j < 4; j++) {                                               \
            int r = bR + 8 * j;                                                     \
            const float* g = B + (size_t)((k0) + r) * M + cb + bC;                  \
            unsigned d = bs_ + (unsigned)(r * BP + bC) * 4u;                        \
            asm volatile("cp.async.cg.shared.global [%0], [%1], 16;\n"              \
                         :: "r"(d), "l"(g));                                        \
        }                                                                           \
        asm volatile("cp.async.commit_group;\n");                                   \
    }

    ISSUE_STAGE(0, 0);
    if (NIT > 1) { ISSUE_STAGE(1, GBK); }
    else { asm volatile("cp.async.commit_group;\n"); }

    for (int it = 0; it < NIT; it++) {
        int cur = it % NSTAGE;
        asm volatile("cp.async.wait_group 1;\n");
        __syncthreads();
        if (it + 2 < NIT) { ISSUE_STAGE((it + 2) % NSTAGE, (it + 2) * GBK); }
        else { asm volatile("cp.async.commit_group;\n"); }

        unsigned as_ = asb[cur], bs_ = bsb[cur];
        unsigned abase = as_ + (unsigned)(lrow * AP + lcol) * 4u;
        #pragma unroll
        for (int ks = 0; ks < 4; ks++) {
            int kk = ks * 8;
            unsigned a[4][4];
            #pragma unroll
            for (int mt = 0; mt < 4; mt++) {
                unsigned addr = abase + (unsigned)(mt * 16 * AP + kk) * 4u;
                asm volatile(
                    "ldmatrix.sync.aligned.m8n8.x4.shared.b16 {%0,%1,%2,%3}, [%4];\n"
                    : "=r"(a[mt][0]), "=r"(a[mt][1]), "=r"(a[mt][2]), "=r"(a[mt][3])
                    : "r"(addr));
            }
            unsigned b[4][2];
            #pragma unroll
            for (int nt = 0; nt < 4; nt++) {
                int cc = wn + nt * 8 + grp;
                float b0, b1;
                unsigned ad0 = bs_ + (unsigned)((kk + qr) * BP + cc) * 4u;
                unsigned ad1 = bs_ + (unsigned)((kk + qr + 4) * BP + cc) * 4u;
                asm volatile("ld.shared.f32 %0, [%1];\n" : "=f"(b0) : "r"(ad0));
                asm volatile("ld.shared.f32 %0, [%1];\n" : "=f"(b1) : "r"(ad1));
                b[nt][0] = __float_as_uint(b0);
                b[nt][1] = __float_as_uint(b1);
            }
            #pragma unroll
            for (int mt = 0; mt < 4; mt++)
                #pragma unroll
                for (int nt = 0; nt < 4; nt++) {
                    asm volatile(
                        "mma.sync.aligned.m16n8k8.row.col.f32.tf32.tf32.f32 "
                        "{%0,%1,%2,%3}, {%4,%5,%6,%7}, {%8,%9}, {%0,%1,%2,%3};\n"
                        : "+f"(acc[mt][nt][0]), "+f"(acc[mt][nt][1]),
                          "+f"(acc[mt][nt][2]), "+f"(acc[mt][nt][3])
                        : "r"(a[mt][0]), "r"(a[mt][1]), "r"(a[mt][2]), "r"(a[mt][3]),
                          "r"(b[nt][0]), "r"(b[nt][1]));
                }
        }
    }

    #pragma unroll
    for (int mt = 0; mt < 4; mt++) {
        int r0 = rb + wm + mt * 16 + grp;
        #pragma unroll
        for (int nt = 0; nt < 4; nt++) {
            int c0 = cb + wn + nt * 8 + qr * 2;
            if (r0 < N)
                *(float2*)(C + (size_t)r0 * M + c0) =
                    make_float2(acc[mt][nt][0], acc[mt][nt][1]);
            if (r0 + 8 < N)
                *(float2*)(C + (size_t)(r0 + 8) * M + c0) =
                    make_float2(acc[mt][nt][2], acc[mt][nt][3]);
        }
    }
}

// ---------------- attention logits: el/er [N,H] (float4) --------------------
__global__ void k_logits(const float4* __restrict__ feat4,
                         const float4* __restrict__ al4, const float4* __restrict__ ar4,
                         float* __restrict__ el, float* __restrict__ er, int H) {
    int w = (blockIdx.x * blockDim.x + threadIdx.x) >> 5;
    int lane = threadIdx.x & 31;
    if (w >= N_NODES * H) return;
    int n = w / H, h = w - n * H;
    float4 f = feat4[(size_t)n * H * 32 + h * 32 + lane];
    float4 a = al4[h * 32 + lane];
    float4 b = ar4[h * 32 + lane];
    float sl = f.x * a.x + f.y * a.y + f.z * a.z + f.w * a.w;
    float sr = f.x * b.x + f.y * b.y + f.z * b.z + f.w * b.w;
    #pragma unroll
    for (int o = 16; o; o >>= 1) {
        sl += __shfl_down_sync(0xffffffffu, sl, o);
        sr += __shfl_down_sync(0xffffffffu, sr, o);
    }
    if (lane == 0) { el[n * H + h] = sl; er[n * H + h] = sr; }
}

// ---------------- per-(dst,head) softmax weights ----------------------------
__global__ void k_alpha(const float* __restrict__ el, const float* __restrict__ er,
                        const int* __restrict__ ssrc, const int* __restrict__ off,
                        float* __restrict__ alpha, int H) {
    int idx = blockIdx.x * blockDim.x + threadIdx.x;
    if (idx >= N_NODES * H) return;
    int n = idx / H, h = idx - n * H;
    int beg = off[n], end = off[n + 1];
    float er_nh = er[n * H + h];
    float m = -INFINITY;
    for (int i = beg; i < end; i++) {
        float x = el[ssrc[i] * H + h] + er_nh;
        x = (x > 0.f) ? x : 0.2f * x;     // leaky_relu 0.2
        alpha[(size_t)i * H + h] = x;
        m = fmaxf(m, x);
    }
    float s = 0.f;
    for (int i = beg; i < end; i++) {
        float p = __expf(alpha[(size_t)i * H + h] - m);
        alpha[(size_t)i * H + h] = p;
        s += p;
    }
    float inv = 1.f / fmaxf(s, 1e-9f);
    for (int i = beg; i < end; i++)
        alpha[(size_t)i * H + h] *= inv;
}

// ---------------- weighted gather-aggregate (float4) ------------------------
// rnd: round outputs to tf32 (they feed the next layer's GEMM)
__global__ void k_aggregate(const float4* __restrict__ feat4,
                            const int* __restrict__ ssrc,
                            const int* __restrict__ off,
                            const float* __restrict__ alpha,
                            const float4* __restrict__ res4,
                            const float4* __restrict__ bias4,
                            float4* __restrict__ out4, int H, int act, int rnd) {
    int n = blockIdx.x;
    int tid = threadIdx.x;        // h*32 + d4
    int h = tid >> 5;
    int HD4 = H * 32;
    int beg = off[n], end = off[n + 1];
    float4 acc = make_float4(0.f, 0.f, 0.f, 0.f);
    for (int i = beg; i < end; i++) {
        int sn = ssrc[i];
        float w = alpha[(size_t)i * H + h];
        float4 f = feat4[(size_t)sn * HD4 + tid];
        acc.x += w * f.x; acc.y += w * f.y;
        acc.z += w * f.z; acc.w += w * f.w;
    }
    if (res4 != nullptr) {
        float4 r = res4[(size_t)n * HD4 + tid];
        acc.x += r.x; acc.y += r.y; acc.z += r.z; acc.w += r.w;
    }
    float4 b = bias4[tid];
    acc.x += b.x; acc.y += b.y; acc.z += b.z; acc.w += b.w;
    if (act) {
        acc.x = (acc.x > 0.f) ? acc.x : expm1f(acc.x);
        acc.y = (acc.y > 0.f) ? acc.y : expm1f(acc.y);
        acc.z = (acc.z > 0.f) ? acc.z : expm1f(acc.z);
        acc.w = (acc.w > 0.f) ? acc.w : expm1f(acc.w);
    }
    if (rnd) {
        acc.x = f2tf32(acc.x); acc.y = f2tf32(acc.y);
        acc.z = f2tf32(acc.z); acc.w = f2tf32(acc.w);
    }
    out4[(size_t)n * HD4 + tid] = acc;
}

// ---------------- head-mean + graph pooling ---------------------------------
__global__ void k_local_pool(const float* __restrict__ x3,
                             const int* __restrict__ gid,
                             float* __restrict__ local,
                             float* gsum, int* gcnt) {
    int n = blockIdx.x;
    int d = threadIdx.x;   // 128
    float v = 0.f;
    #pragma unroll
    for (int h = 0; h < 6; h++) v += x3[(size_t)n * 768 + h * DIM + d];
    v *= (1.f / 6.f);
    local[(size_t)n * DIM + d] = v;
    int g = gid[n];
    atomicAdd(&gsum[g * DIM + d], v);
    if (d == 0) atomicAdd(&gcnt[g], 1);
}

__global__ void k_global_fc(const float* __restrict__ gsum, const int* __restrict__ gcnt,
                            const float* __restrict__ Wm, const float* __restrict__ bm,
                            float* __restrict__ out) {
    int g = blockIdx.x;
    int m = threadIdx.x;   // 128
    __shared__ float p[DIM];
    float c = fmaxf((float)gcnt[g], 1.f);
    p[m] = gsum[g * DIM + m] / c;
    __syncthreads();
    float acc = bm[m];
    #pragma unroll
    for (int d = 0; d < DIM; d++) acc += p[d] * Wm[d * DIM + m];
    out[(size_t)g * DIM + m] = acc;
}

// ---------------- launch ----------------------------------------------------
extern "C" void kernel_launch(void* const* d_in, const int* in_sizes, int n_in,
                              void* d_out, int out_size) {
    const float* h    = (const float*)d_in[0];
    // d_in[1] = he (unused)
    const int*   src  = (const int*)d_in[2];
    const int*   dst  = (const int*)d_in[3];
    const int*   gid  = (const int*)d_in[4];
    const float* W0   = (const float*)d_in[5];
    const float* al0  = (const float*)d_in[6];
    const float* ar0  = (const float*)d_in[7];
    const float* b0   = (const float*)d_in[8];
    const float* W1   = (const float*)d_in[9];
    const float* al1  = (const float*)d_in[10];
    const float* ar1  = (const float*)d_in[11];
    const float* b1   = (const float*)d_in[12];
    const float* W2   = (const float*)d_in[13];
    const float* al2  = (const float*)d_in[14];
    const float* ar2  = (const float*)d_in[15];
    const float* b2   = (const float*)d_in[16];
    const float* resW2= (const float*)d_in[17];
    const float* Wm   = (const float*)d_in[18];
    const float* bm   = (const float*)d_in[19];
    float* out = (float*)d_out;

    static int smem_set = 0;
    if (!smem_set) {
        cudaFuncSetAttribute(k_tf32gemm, cudaFuncAttributeMaxDynamicSharedMemorySize,
                             GEMM_SMEM);
        smem_set = 1;
    }

    void *pfeat, *px1, *px2, *pres, *px3, *pel, *per, *palpha, *pcounts, *poff,
         *pcursor, *pssrc, *pgsum, *pgcnt, *pwr;
    cudaGetSymbolAddress(&pfeat, g_feat);
    cudaGetSymbolAddress(&px1, g_x1);
    cudaGetSymbolAddress(&px2, g_x2);
    cudaGetSymbolAddress(&pres, g_res);
    cudaGetSymbolAddress(&px3, g_x3);
    cudaGetSymbolAddress(&pel, g_el);
    cudaGetSymbolAddress(&per, g_er);
    cudaGetSymbolAddress(&palpha, g_alpha);
    cudaGetSymbolAddress(&pcounts, g_counts);
    cudaGetSymbolAddress(&poff, g_off);
    cudaGetSymbolAddress(&pcursor, g_cursor);
    cudaGetSymbolAddress(&pssrc, g_ssrc);
    cudaGetSymbolAddress(&pgsum, g_gsum);
    cudaGetSymbolAddress(&pgcnt, g_gcnt);
    cudaGetSymbolAddress(&pwr, g_wr);
    float* feat = (float*)pfeat;
    float* x1 = (float*)px1;
    float* x2 = (float*)px2;
    float* res = (float*)pres;
    float* x3 = (float*)px3;
    float* el = (float*)pel;
    float* er = (float*)per;
    float* alpha = (float*)palpha;
    int* counts = (int*)pcounts;
    int* off = (int*)poff;
    int* cursor = (int*)pcursor;
    int* ssrc = (int*)pssrc;
    float* gsum = (float*)pgsum;
    int* gcnt = (int*)pgcnt;
    float* wr = (float*)pwr;

    // rounded-weight layout inside g_wr
    float* W0r = wr;                 // 128*512  = 65536
    float* W1r = wr + 65536;         // 512*512  = 262144
    float* W2r = wr + 327680;        // 512*768  = 393216
    float* rW2r = wr + 720896;       // 512*768  = 393216
    float* hr = x3;                  // rounded h lives in x3 (free until layer 2)

    const int N = N_NODES, E = N_EDGES;
    dim3 gemmBlk(256);
    int gy = (N + GBM - 1) / GBM;

    // ---- pre-round GEMM inputs (weights + h) ----
    k_round4<<<(65536 / 4 + 255) / 256, 256>>>((const float4*)W0, (float4*)W0r, 65536 / 4);
    k_round4<<<(262144 / 4 + 255) / 256, 256>>>((const float4*)W1, (float4*)W1r, 262144 / 4);
    k_round4<<<(393216 / 4 + 255) / 256, 256>>>((const float4*)W2, (float4*)W2r, 393216 / 4);
    k_round4<<<(393216 / 4 + 255) / 256, 256>>>((const float4*)resW2, (float4*)rW2r, 393216 / 4);
    k_round4<<<(N * DIM / 4 + 255) / 256, 256>>>((const float4*)h, (float4*)hr, N * DIM / 4);

    // ---- CSR build ----
    k_zero_int<<<(N + 255) / 256, 256>>>(counts, N);
    k_count<<<(E + 255) / 256, 256>>>(dst, counts, E);
    k_scan<<<1, 1024>>>(counts, off, cursor, N);
    k_fill<<<(E + 255) / 256, 256>>>(dst, src, cursor, ssrc, E);

    // ---- layer 0: H=4, no residual, elu ----
    {
        dim3 grid(512 / GBN, gy);
        k_tf32gemm<<<grid, gemmBlk, GEMM_SMEM>>>(hr, W0r, feat, N, 128, 512);
        int warps = N * 4;
        k_logits<<<(warps * 32 + 255) / 256, 256>>>((const float4*)feat,
            (const float4*)al0, (const float4*)ar0, el, er, 4);
        k_alpha<<<(N * 4 + 255) / 256, 256>>>(el, er, ssrc, off, alpha, 4);
        k_aggregate<<<N, 128>>>((const float4*)feat, ssrc, off, alpha,
            nullptr, (const float4*)b0, (float4*)x1, 4, 1, 1);
    }
    // ---- layer 1: H=4, identity residual, elu ----
    {
        dim3 grid(512 / GBN, gy);
        k_tf32gemm<<<grid, gemmBlk, GEMM_SMEM>>>(x1, W1r, feat, N, 512, 512);
        int warps = N * 4;
        k_logits<<<(warps * 32 + 255) / 256, 256>>>((const float4*)feat,
            (const float4*)al1, (const float4*)ar1, el, er, 4);
        k_alpha<<<(N * 4 + 255) / 256, 256>>>(el, er, ssrc, off, alpha, 4);
        k_aggregate<<<N, 128>>>((const float4*)feat, ssrc, off, alpha,
            (const float4*)x1, (const float4*)b1, (float4*)x2, 4, 1, 1);
    }
    // ---- layer 2: H=6, linear residual, no act ----
    {
        dim3 grid(768 / GBN, gy);
        k_tf32gemm<<<grid, gemmBlk, GEMM_SMEM>>>(x2, W2r, feat, N, 512, 768);
        k_tf32gemm<<<grid, gemmBlk, GEMM_SMEM>>>(x2, rW2r, res, N, 512, 768);
        int warps = N * 6;
        k_logits<<<(warps * 32 + 255) / 256, 256>>>((const float4*)feat,
            (const float4*)al2, (const float4*)ar2, el, er, 6);
        k_alpha<<<(N * 6 + 255) / 256, 256>>>(el, er, ssrc, off, alpha, 6);
        k_aggregate<<<N, 192>>>((const float4*)feat, ssrc, off, alpha,
            (const float4*)res, (const float4*)b2, (float4*)x3, 6, 0, 0);
    }
    // ---- head mean + graph pooling + final linear ----
    k_zero_float<<<(N_GRAPHS * DIM + 255) / 256, 256>>>(gsum, N_GRAPHS * DIM);
    k_zero_int<<<1, 64>>>(gcnt, N_GRAPHS);
    k_local_pool<<<N, DIM>>>(x3, gid, out, gsum, gcnt);
    k_global_fc<<<N_GRAPHS, DIM>>>(gsum, gcnt, Wm, bm, out + (size_t)N * DIM);
}

// round 6
// speedup vs baseline: 1.0049x; 1.0049x over previous
#include <cuda_runtime.h>
#include <math.h>

#define N_NODES 20000
#define N_EDGES 320000
#define N_GRAPHS 64
#define DIM 128

// ---------------- scratch (device globals; no allocation allowed) ----------
__device__ float g_feat[N_NODES * 768];   // per-layer fc output [N, H*D]
__device__ float g_x1[N_NODES * 512];     // layer0 output (tf32-rounded)
__device__ float g_x2[N_NODES * 512];     // layer1 output (tf32-rounded)
__device__ float g_res[N_NODES * 768];    // layer2 linear residual
__device__ float g_x3[N_NODES * 768];     // layer2 output; front also holds rounded h
__device__ float g_el[N_NODES * 6];
__device__ float g_er[N_NODES * 6];
__device__ float g_alpha[N_EDGES * 6];    // normalized attn weights (sorted order)
__device__ int   g_counts[N_NODES];
__device__ int   g_off[N_NODES + 1];
__device__ int   g_cursor[N_NODES];
__device__ int   g_ssrc[N_EDGES];         // src node per sorted edge slot
__device__ float g_gsum[N_GRAPHS * DIM];
__device__ int   g_gcnt[N_GRAPHS];
__device__ float g_wr[1114112];           // rounded weights: W0|W1|W2|resW2

__device__ __forceinline__ float f2tf32(float x) {
    unsigned r;
    asm("cvt.rna.tf32.f32 %0, %1;" : "=r"(r) : "f"(x));
    return __uint_as_float(r);
}

// ---------------- small utility kernels ------------------------------------
__global__ void k_zero_int(int* p, int n) {
    int i = blockIdx.x * blockDim.x + threadIdx.x;
    if (i < n) p[i] = 0;
}
__global__ void k_zero_float(float* p, int n) {
    int i = blockIdx.x * blockDim.x + threadIdx.x;
    if (i < n) p[i] = 0.f;
}
__global__ void k_round4(const float4* __restrict__ in, float4* __restrict__ out, int n4) {
    int i = blockIdx.x * blockDim.x + threadIdx.x;
    if (i < n4) {
        float4 v = in[i];
        v.x = f2tf32(v.x); v.y = f2tf32(v.y);
        v.z = f2tf32(v.z); v.w = f2tf32(v.w);
        out[i] = v;
    }
}
__global__ void k_count(const int* __restrict__ dst, int* counts, int E) {
    int e = blockIdx.x * blockDim.x + threadIdx.x;
    if (e < E) atomicAdd(&counts[dst[e]], 1);
}

// single-block shuffle scan: off[0]=0, off[i+1]=off[i]+counts[i]; cursor[i]=off[i]
__global__ void k_scan(const int* __restrict__ counts, int* off, int* cursor, int n) {
    __shared__ int warp_sums[32];
    __shared__ int carry_s;
    int t = threadIdx.x, lane = t & 31, w = t >> 5;
    if (t == 0) { carry_s = 0; off[0] = 0; }
    __syncthreads();
    for (int base = 0; base < n; base += 1024) {
        int v = (base + t < n) ? counts[base + t] : 0;
        int x = v;
        #pragma unroll
        for (int o = 1; o < 32; o <<= 1) {
            int y = __shfl_up_sync(0xffffffffu, x, o);
            if (lane >= o) x += y;
        }
        if (lane == 31) warp_sums[w] = x;
        __syncthreads();
        if (w == 0) {
            int s = warp_sums[lane];
            #pragma unroll
            for (int o = 1; o < 32; o <<= 1) {
                int y = __shfl_up_sync(0xffffffffu, s, o);
                if (lane >= o) s += y;
            }
            warp_sums[lane] = s;
        }
        __syncthreads();
        int pre = (w > 0) ? warp_sums[w - 1] : 0;
        int incl = x + pre + carry_s;
        if (base + t < n) {
            off[base + t + 1] = incl;
            cursor[base + t] = incl - v;
        }
        __syncthreads();
        if (t == 0) carry_s += warp_sums[31];
        __syncthreads();
    }
}
__global__ void k_fill(const int* __restrict__ dst, const int* __restrict__ src,
                       int* cursor, int* ssrc, int E) {
    int e = blockIdx.x * blockDim.x + threadIdx.x;
    if (e < E) {
        int pos = atomicAdd(&cursor[dst[e]], 1);
        ssrc[pos] = src[e];
    }
}

// ---------------- TF32 tensor-core GEMM: C[N,M]=A[N,K]@B[K,M] row-major -----
// Inputs MUST be pre-rounded to tf32. 128x128x32 tile, 3-stage cp.async,
// ldmatrix A fragments, zero cvt in mainloop.
#define GBM 128
#define GBN 128
#define GBK 32
#define AP 36    // A smem pitch (floats)
#define BP 136   // B smem pitch (floats)
#define AS_FLOATS (GBM * AP)                 // 4608
#define BS_FLOATS (GBK * BP)                 // 4352
#define STAGE_FLOATS (AS_FLOATS + BS_FLOATS) // 8960
#define NSTAGE 3
#define GEMM_SMEM (NSTAGE * STAGE_FLOATS * 4)  // 107520 bytes

__global__ __launch_bounds__(256)
void k_tf32gemm(const float* __restrict__ A, const float* __restrict__ B,
                float* __restrict__ C, int N, int K, int M) {
    extern __shared__ float sm[];
    int t = threadIdx.x;
    int warp = t >> 5, lane = t & 31;
    int grp = lane >> 2;   // 0..7
    int qr  = lane & 3;    // 0..3
    int wm = (warp >> 2) * 64;   // 2x4 warp grid -> 64x32 warp tiles
    int wn = (warp & 3) * 32;
    int rb = blockIdx.y * GBM;
    int cb = blockIdx.x * GBN;

    float acc[4][4][4];
    #pragma unroll
    for (int i = 0; i < 4; i++)
        #pragma unroll
        for (int j = 0; j < 4; j++)
            #pragma unroll
            for (int k = 0; k < 4; k++) acc[i][j][k] = 0.f;

    unsigned smbase = (unsigned)__cvta_generic_to_shared(sm);
    unsigned asb[NSTAGE], bsb[NSTAGE];
    #pragma unroll
    for (int s = 0; s < NSTAGE; s++) {
        asb[s] = smbase + (unsigned)(s * STAGE_FLOATS) * 4u;
        bsb[s] = asb[s] + AS_FLOATS * 4u;
    }

    int aR = t >> 3;          // 0..31 (+32j)
    int aC = (t & 7) * 4;
    int bR = t >> 5;          // 0..7  (+8j)
    int bC = (t & 31) * 4;

    int sub = lane >> 3, li = lane & 7;
    int lrow = wm + ((sub & 1) << 3) + li;
    int lcol = (sub & 2) ? 4 : 0;

    int NIT = K / GBK;

    #define ISSUE_STAGE(s, k0)                                                      \
    {                                                                               \
        unsigned as_ = asb[s], bs_ = bsb[s];                                        \
        _Pragma("unroll")                                                           \
        for (int j = 0; j < 4; j++) {                                               \
            int r = aR + 32 * j;                                                    \
            int gr = rb + r;                                                        \
            int sz = (gr < N) ? 16 : 0;                                             \
            const float* g = A + (size_t)(gr < N ? gr : 0) * K + (k0) + aC;         \
            unsigned d = as_ + (unsigned)(r * AP + aC) * 4u;                        \
            asm volatile("cp.async.cg.shared.global [%0], [%1], 16, %2;\n"          \
                         :: "r"(d), "l"(g), "r"(sz));                               \
        }                                                                           \
        _Pragma("unroll")                                                           \
        for (int j = 0; j < 4; j++) {                                               \
            int r = bR + 8 * j;                                                     \
            const float* g = B + (size_t)((k0) + r) * M + cb + bC;                  \
            unsigned d = bs_ + (unsigned)(r * BP + bC) * 4u;                        \
            asm volatile("cp.async.cg.shared.global [%0], [%1], 16;\n"              \
                         :: "r"(d), "l"(g));                                        \
        }                                                                           \
        asm volatile("cp.async.commit_group;\n");                                   \
    }

    ISSUE_STAGE(0, 0);
    if (NIT > 1) { ISSUE_STAGE(1, GBK); }
    else { asm volatile("cp.async.commit_group;\n"); }

    for (int it = 0; it < NIT; it++) {
        int cur = it % NSTAGE;
        asm volatile("cp.async.wait_group 1;\n");
        __syncthreads();
        if (it + 2 < NIT) { ISSUE_STAGE((it + 2) % NSTAGE, (it + 2) * GBK); }
        else { asm volatile("cp.async.commit_group;\n"); }

        unsigned as_ = asb[cur], bs_ = bsb[cur];
        unsigned abase = as_ + (unsigned)(lrow * AP + lcol) * 4u;
        #pragma unroll
        for (int ks = 0; ks < 4; ks++) {
            int kk = ks * 8;
            unsigned a[4][4];
            #pragma unroll
            for (int mt = 0; mt < 4; mt++) {
                unsigned addr = abase + (unsigned)(mt * 16 * AP + kk) * 4u;
                asm volatile(
                    "ldmatrix.sync.aligned.m8n8.x4.shared.b16 {%0,%1,%2,%3}, [%4];\n"
                    : "=r"(a[mt][0]), "=r"(a[mt][1]), "=r"(a[mt][2]), "=r"(a[mt][3])
                    : "r"(addr));
            }
            unsigned b[4][2];
            #pragma unroll
            for (int nt = 0; nt < 4; nt++) {
                int cc = wn + nt * 8 + grp;
                float b0, b1;
                unsigned ad0 = bs_ + (unsigned)((kk + qr) * BP + cc) * 4u;
                unsigned ad1 = bs_ + (unsigned)((kk + qr + 4) * BP + cc) * 4u;
                asm volatile("ld.shared.f32 %0, [%1];\n" : "=f"(b0) : "r"(ad0));
                asm volatile("ld.shared.f32 %0, [%1];\n" : "=f"(b1) : "r"(ad1));
                b[nt][0] = __float_as_uint(b0);
                b[nt][1] = __float_as_uint(b1);
            }
            #pragma unroll
            for (int mt = 0; mt < 4; mt++)
                #pragma unroll
                for (int nt = 0; nt < 4; nt++) {
                    asm volatile(
                        "mma.sync.aligned.m16n8k8.row.col.f32.tf32.tf32.f32 "
                        "{%0,%1,%2,%3}, {%4,%5,%6,%7}, {%8,%9}, {%0,%1,%2,%3};\n"
                        : "+f"(acc[mt][nt][0]), "+f"(acc[mt][nt][1]),
                          "+f"(acc[mt][nt][2]), "+f"(acc[mt][nt][3])
                        : "r"(a[mt][0]), "r"(a[mt][1]), "r"(a[mt][2]), "r"(a[mt][3]),
                          "r"(b[nt][0]), "r"(b[nt][1]));
                }
        }
    }

    #pragma unroll
    for (int mt = 0; mt < 4; mt++) {
        int r0 = rb + wm + mt * 16 + grp;
        #pragma unroll
        for (int nt = 0; nt < 4; nt++) {
            int c0 = cb + wn + nt * 8 + qr * 2;
            if (r0 < N)
                *(float2*)(C + (size_t)r0 * M + c0) =
                    make_float2(acc[mt][nt][0], acc[mt][nt][1]);
            if (r0 + 8 < N)
                *(float2*)(C + (size_t)(r0 + 8) * M + c0) =
                    make_float2(acc[mt][nt][2], acc[mt][nt][3]);
        }
    }
}

// ---------------- attention logits: el/er [N,H] (float4) --------------------
__global__ void k_logits(const float4* __restrict__ feat4,
                         const float4* __restrict__ al4, const float4* __restrict__ ar4,
                         float* __restrict__ el, float* __restrict__ er, int H) {
    int w = (blockIdx.x * blockDim.x + threadIdx.x) >> 5;
    int lane = threadIdx.x & 31;
    if (w >= N_NODES * H) return;
    int n = w / H, h = w - n * H;
    float4 f = feat4[(size_t)n * H * 32 + h * 32 + lane];
    float4 a = al4[h * 32 + lane];
    float4 b = ar4[h * 32 + lane];
    float sl = f.x * a.x + f.y * a.y + f.z * a.z + f.w * a.w;
    float sr = f.x * b.x + f.y * b.y + f.z * b.z + f.w * b.w;
    #pragma unroll
    for (int o = 16; o; o >>= 1) {
        sl += __shfl_down_sync(0xffffffffu, sl, o);
        sr += __shfl_down_sync(0xffffffffu, sr, o);
    }
    if (lane == 0) { el[n * H + h] = sl; er[n * H + h] = sr; }
}

// ---------------- per-(dst,head) softmax weights ----------------------------
__global__ void k_alpha(const float* __restrict__ el, const float* __restrict__ er,
                        const int* __restrict__ ssrc, const int* __restrict__ off,
                        float* __restrict__ alpha, int H) {
    int idx = blockIdx.x * blockDim.x + threadIdx.x;
    if (idx >= N_NODES * H) return;
    int n = idx / H, h = idx - n * H;
    int beg = off[n], end = off[n + 1];
    float er_nh = er[n * H + h];
    float m = -INFINITY;
    for (int i = beg; i < end; i++) {
        float x = el[ssrc[i] * H + h] + er_nh;
        x = (x > 0.f) ? x : 0.2f * x;     // leaky_relu 0.2
        alpha[(size_t)i * H + h] = x;
        m = fmaxf(m, x);
    }
    float s = 0.f;
    for (int i = beg; i < end; i++) {
        float p = __expf(alpha[(size_t)i * H + h] - m);
        alpha[(size_t)i * H + h] = p;
        s += p;
    }
    float inv = 1.f / fmaxf(s, 1e-9f);
    for (int i = beg; i < end; i++)
        alpha[(size_t)i * H + h] *= inv;
}

// ---------------- weighted gather-aggregate (float4) ------------------------
// rnd: round outputs to tf32 (they feed the next layer's GEMM)
__global__ void k_aggregate(const float4* __restrict__ feat4,
                            const int* __restrict__ ssrc,
                            const int* __restrict__ off,
                            const float* __restrict__ alpha,
                            const float4* __restrict__ res4,
                            const float4* __restrict__ bias4,
                            float4* __restrict__ out4, int H, int act, int rnd) {
    int n = blockIdx.x;
    int tid = threadIdx.x;        // h*32 + d4
    int h = tid >> 5;
    int HD4 = H * 32;
    int beg = off[n], end = off[n + 1];
    float4 acc = make_float4(0.f, 0.f, 0.f, 0.f);
    for (int i = beg; i < end; i++) {
        int sn = ssrc[i];
        float w = alpha[(size_t)i * H + h];
        float4 f = feat4[(size_t)sn * HD4 + tid];
        acc.x += w * f.x; acc.y += w * f.y;
        acc.z += w * f.z; acc.w += w * f.w;
    }
    if (res4 != nullptr) {
        float4 r = res4[(size_t)n * HD4 + tid];
        acc.x += r.x; acc.y += r.y; acc.z += r.z; acc.w += r.w;
    }
    float4 b = bias4[tid];
    acc.x += b.x; acc.y += b.y; acc.z += b.z; acc.w += b.w;
    if (act) {
        acc.x = (acc.x > 0.f) ? acc.x : expm1f(acc.x);
        acc.y = (acc.y > 0.f) ? acc.y : expm1f(acc.y);
        acc.z = (acc.z > 0.f) ? acc.z : expm1f(acc.z);
        acc.w = (acc.w > 0.f) ? acc.w : expm1f(acc.w);
    }
    if (rnd) {
        acc.x = f2tf32(acc.x); acc.y = f2tf32(acc.y);
        acc.z = f2tf32(acc.z); acc.w = f2tf32(acc.w);
    }
    out4[(size_t)n * HD4 + tid] = acc;
}

// ---------------- head-mean + graph pooling ---------------------------------
__global__ void k_local_pool(const float* __restrict__ x3,
                             const int* __restrict__ gid,
                             float* __restrict__ local,
                             float* gsum, int* gcnt) {
    int n = blockIdx.x;
    int d = threadIdx.x;   // 128
    float v = 0.f;
    #pragma unroll
    for (int h = 0; h < 6; h++) v += x3[(size_t)n * 768 + h * DIM + d];
    v *= (1.f / 6.f);
    local[(size_t)n * DIM + d] = v;
    int g = gid[n];
    atomicAdd(&gsum[g * DIM + d], v);
    if (d == 0) atomicAdd(&gcnt[g], 1);
}

__global__ void k_global_fc(const float* __restrict__ gsum, const int* __restrict__ gcnt,
                            const float* __restrict__ Wm, const float* __restrict__ bm,
                            float* __restrict__ out) {
    int g = blockIdx.x;
    int m = threadIdx.x;   // 128
    __shared__ float p[DIM];
    float c = fmaxf((float)gcnt[g], 1.f);
    p[m] = gsum[g * DIM + m] / c;
    __syncthreads();
    float acc = bm[m];
    #pragma unroll
    for (int d = 0; d < DIM; d++) acc += p[d] * Wm[d * DIM + m];
    out[(size_t)g * DIM + m] = acc;
}

// ---------------- launch ----------------------------------------------------
extern "C" void kernel_launch(void* const* d_in, const int* in_sizes, int n_in,
                              void* d_out, int out_size) {
    const float* h    = (const float*)d_in[0];
    // d_in[1] = he (unused)
    const int*   src  = (const int*)d_in[2];
    const int*   dst  = (const int*)d_in[3];
    const int*   gid  = (const int*)d_in[4];
    const float* W0   = (const float*)d_in[5];
    const float* al0  = (const float*)d_in[6];
    const float* ar0  = (const float*)d_in[7];
    const float* b0   = (const float*)d_in[8];
    const float* W1   = (const float*)d_in[9];
    const float* al1  = (const float*)d_in[10];
    const float* ar1  = (const float*)d_in[11];
    const float* b1   = (const float*)d_in[12];
    const float* W2   = (const float*)d_in[13];
    const float* al2  = (const float*)d_in[14];
    const float* ar2  = (const float*)d_in[15];
    const float* b2   = (const float*)d_in[16];
    const float* resW2= (const float*)d_in[17];
    const float* Wm   = (const float*)d_in[18];
    const float* bm   = (const float*)d_in[19];
    float* out = (float*)d_out;

    static int smem_set = 0;
    if (!smem_set) {
        cudaFuncSetAttribute(k_tf32gemm, cudaFuncAttributeMaxDynamicSharedMemorySize,
                             GEMM_SMEM);
        smem_set = 1;
    }

    void *pfeat, *px1, *px2, *pres, *px3, *pel, *per, *palpha, *pcounts, *poff,
         *pcursor, *pssrc, *pgsum, *pgcnt, *pwr;
    cudaGetSymbolAddress(&pfeat, g_feat);
    cudaGetSymbolAddress(&px1, g_x1);
    cudaGetSymbolAddress(&px2, g_x2);
    cudaGetSymbolAddress(&pres, g_res);
    cudaGetSymbolAddress(&px3, g_x3);
    cudaGetSymbolAddress(&pel, g_el);
    cudaGetSymbolAddress(&per, g_er);
    cudaGetSymbolAddress(&palpha, g_alpha);
    cudaGetSymbolAddress(&pcounts, g_counts);
    cudaGetSymbolAddress(&poff, g_off);
    cudaGetSymbolAddress(&pcursor, g_cursor);
    cudaGetSymbolAddress(&pssrc, g_ssrc);
    cudaGetSymbolAddress(&pgsum, g_gsum);
    cudaGetSymbolAddress(&pgcnt, g_gcnt);
    cudaGetSymbolAddress(&pwr, g_wr);
    float* feat = (float*)pfeat;
    float* x1 = (float*)px1;
    float* x2 = (float*)px2;
    float* res = (float*)pres;
    float* x3 = (float*)px3;
    float* el = (float*)pel;
    float* er = (float*)per;
    float* alpha = (float*)palpha;
    int* counts = (int*)pcounts;
    int* off = (int*)poff;
    int* cursor = (int*)pcursor;
    int* ssrc = (int*)pssrc;
    float* gsum = (float*)pgsum;
    int* gcnt = (int*)pgcnt;
    float* wr = (float*)pwr;

    // rounded-weight layout inside g_wr
    float* W0r = wr;                 // 128*512  = 65536
    float* W1r = wr + 65536;         // 512*512  = 262144
    float* W2r = wr + 327680;        // 512*768  = 393216
    float* rW2r = wr + 720896;       // 512*768  = 393216
    float* hr = x3;                  // rounded h lives in x3 (free until layer 2)

    const int N = N_NODES, E = N_EDGES;
    dim3 gemmBlk(256);
    int gy = (N + GBM - 1) / GBM;

    // ---- pre-round GEMM inputs (weights + h) ----
    k_round4<<<(65536 / 4 + 255) / 256, 256>>>((const float4*)W0, (float4*)W0r, 65536 / 4);
    k_round4<<<(262144 / 4 + 255) / 256, 256>>>((const float4*)W1, (float4*)W1r, 262144 / 4);
    k_round4<<<(393216 / 4 + 255) / 256, 256>>>((const float4*)W2, (float4*)W2r, 393216 / 4);
    k_round4<<<(393216 / 4 + 255) / 256, 256>>>((const float4*)resW2, (float4*)rW2r, 393216 / 4);
    k_round4<<<(N * DIM / 4 + 255) / 256, 256>>>((const float4*)h, (float4*)hr, N * DIM / 4);

    // ---- CSR build ----
    k_zero_int<<<(N + 255) / 256, 256>>>(counts, N);
    k_count<<<(E + 255) / 256, 256>>>(dst, counts, E);
    k_scan<<<1, 1024>>>(counts, off, cursor, N);
    k_fill<<<(E + 255) / 256, 256>>>(dst, src, cursor, ssrc, E);

    // ---- layer 0: H=4, no residual, elu ----
    {
        dim3 grid(512 / GBN, gy);
        k_tf32gemm<<<grid, gemmBlk, GEMM_SMEM>>>(hr, W0r, feat, N, 128, 512);
        int warps = N * 4;
        k_logits<<<(warps * 32 + 255) / 256, 256>>>((const float4*)feat,
            (const float4*)al0, (const float4*)ar0, el, er, 4);
        k_alpha<<<(N * 4 + 255) / 256, 256>>>(el, er, ssrc, off, alpha, 4);
        k_aggregate<<<N, 128>>>((const float4*)feat, ssrc, off, alpha,
            nullptr, (const float4*)b0, (float4*)x1, 4, 1, 1);
    }
    // ---- layer 1: H=4, identity residual, elu ----
    {
        dim3 grid(512 / GBN, gy);
        k_tf32gemm<<<grid, gemmBlk, GEMM_SMEM>>>(x1, W1r, feat, N, 512, 512);
        int warps = N * 4;
        k_logits<<<(warps * 32 + 255) / 256, 256>>>((const float4*)feat,
            (const float4*)al1, (const float4*)ar1, el, er, 4);
        k_alpha<<<(N * 4 + 255) / 256, 256>>>(el, er, ssrc, off, alpha, 4);
        k_aggregate<<<N, 128>>>((const float4*)feat, ssrc, off, alpha,
            (const float4*)x1, (const float4*)b1, (float4*)x2, 4, 1, 1);
    }
    // ---- layer 2: H=6, linear residual, no act ----
    {
        dim3 grid(768 / GBN, gy);
        k_tf32gemm<<<grid, gemmBlk, GEMM_SMEM>>>(x2, W2r, feat, N, 512, 768);
        k_tf32gemm<<<grid, gemmBlk, GEMM_SMEM>>>(x2, rW2r, res, N, 512, 768);
        int warps = N * 6;
        k_logits<<<(warps * 32 + 255) / 256, 256>>>((const float4*)feat,
            (const float4*)al2, (const float4*)ar2, el, er, 6);
        k_alpha<<<(N * 6 + 255) / 256, 256>>>(el, er, ssrc, off, alpha, 6);
        k_aggregate<<<N, 192>>>((const float4*)feat, ssrc, off, alpha,
            (const float4*)res, (const float4*)b2, (float4*)x3, 6, 0, 0);
    }
    // ---- head mean + graph pooling + final linear ----
    k_zero_float<<<(N_GRAPHS * DIM + 255) / 256, 256>>>(gsum, N_GRAPHS * DIM);
    k_zero_int<<<1, 64>>>(gcnt, N_GRAPHS);
    k_local_pool<<<N, DIM>>>(x3, gid, out, gsum, gcnt);
    k_global_fc<<<N_GRAPHS, DIM>>>(gsum, gcnt, Wm, bm, out + (size_t)N * DIM);
}

// round 8
// speedup vs baseline: 1.0221x; 1.0171x over previous
#include <cuda_runtime.h>
#include <math.h>

#define N_NODES 20000
#define N_EDGES 320000
#define N_GRAPHS 64
#define DIM 128

// ---------------- scratch (device globals; no allocation allowed) ----------
__device__ float g_feat[N_NODES * 768];   // per-layer fc output [N, H*D]
__device__ float g_x1[N_NODES * 512];     // layer0 output
__device__ float g_x2[N_NODES * 512];     // layer1 output
__device__ float g_res[N_NODES * 768];    // layer2 linear residual
__device__ float g_el[N_NODES * 6];
__device__ float g_er[N_NODES * 6];
__device__ float g_alpha[N_EDGES * 6];
__device__ int   g_counts[N_NODES];
__device__ int   g_off[N_NODES + 1];
__device__ int   g_cursor[N_NODES];
__device__ int   g_ssrc[N_EDGES];
__device__ float g_gsum[N_GRAPHS * DIM];
__device__ int   g_gcnt[N_GRAPHS];

// ---------------- small utility kernels ------------------------------------
__global__ void k_zero_int(int* p, int n) {
    int i = blockIdx.x * blockDim.x + threadIdx.x;
    if (i < n) p[i] = 0;
}
__global__ void k_zero_float(float* p, int n) {
    int i = blockIdx.x * blockDim.x + threadIdx.x;
    if (i < n) p[i] = 0.f;
}
__global__ void k_count(const int* __restrict__ dst, int* counts, int E) {
    int e = blockIdx.x * blockDim.x + threadIdx.x;
    if (e < E) atomicAdd(&counts[dst[e]], 1);
}
__global__ void k_scan(const int* __restrict__ counts, int* off, int* cursor, int n) {
    __shared__ int warp_sums[32];
    __shared__ int carry_s;
    int t = threadIdx.x, lane = t & 31, w = t >> 5;
    if (t == 0) { carry_s = 0; off[0] = 0; }
    __syncthreads();
    for (int base = 0; base < n; base += 1024) {
        int v = (base + t < n) ? counts[base + t] : 0;
        int x = v;
        #pragma unroll
        for (int o = 1; o < 32; o <<= 1) {
            int y = __shfl_up_sync(0xffffffffu, x, o);
            if (lane >= o) x += y;
        }
        if (lane == 31) warp_sums[w] = x;
        __syncthreads();
        if (w == 0) {
            int s = warp_sums[lane];
            #pragma unroll
            for (int o = 1; o < 32; o <<= 1) {
                int y = __shfl_up_sync(0xffffffffu, s, o);
                if (lane >= o) s += y;
            }
            warp_sums[lane] = s;
        }
        __syncthreads();
        int pre = (w > 0) ? warp_sums[w - 1] : 0;
        int incl = x + pre + carry_s;
        if (base + t < n) {
            off[base + t + 1] = incl;
            cursor[base + t] = incl - v;
        }
        __syncthreads();
        if (t == 0) carry_s += warp_sums[31];
        __syncthreads();
    }
}
__global__ void k_fill(const int* __restrict__ dst, const int* __restrict__ src,
                       int* cursor, int* ssrc, int E) {
    int e = blockIdx.x * blockDim.x + threadIdx.x;
    if (e < E) {
        int pos = atomicAdd(&cursor[dst[e]], 1);
        ssrc[pos] = src[e];
    }
}

// ---------------- TF32 tensor-core GEMM + fused attention logits ------------
// C[N,M] = A[N,K] @ B[K,M], all row-major. 128x128x32 tile, 2-stage cp.async.
// If al != nullptr: each 128-col tile is one head; epilogue also emits
// el[n,h]=dot(C_row, al[h]), er likewise (h = blockIdx.x).
#define GBM 128
#define GBN 128
#define GBK 32
#define AP 36    // A smem pitch (floats)
#define BP 136   // B smem pitch (floats)
#define AS_FLOATS (GBM * AP)                 // 4608
#define BS_FLOATS (GBK * BP)                 // 4352
#define STAGE_FLOATS (AS_FLOATS + BS_FLOATS) // 8960
#define GEMM_SMEM (2 * STAGE_FLOATS * 4)     // 71680 bytes

__global__ __launch_bounds__(256)
void k_tf32gemm(const float* __restrict__ A, const float* __restrict__ B,
                float* __restrict__ C, int N, int K, int M,
                const float* __restrict__ al, const float* __restrict__ ar,
                float* __restrict__ elO, float* __restrict__ erO, int H) {
    extern __shared__ float sm[];
    int t = threadIdx.x;
    int warp = t >> 5, lane = t & 31;
    int grp = lane >> 2;   // 0..7
    int qr  = lane & 3;    // 0..3
    int wm = (warp >> 2) * 64;   // 2x4 warp grid -> 64x32 warp tiles
    int wn_idx = warp & 3;
    int wn = wn_idx * 32;
    int rb = blockIdx.y * GBM;
    int cb = blockIdx.x * GBN;

    float acc[4][4][4];
    #pragma unroll
    for (int i = 0; i < 4; i++)
        #pragma unroll
        for (int j = 0; j < 4; j++)
            #pragma unroll
            for (int k = 0; k < 4; k++) acc[i][j][k] = 0.f;

    unsigned smbase = (unsigned)__cvta_generic_to_shared(sm);
    unsigned asb[2] = { smbase, smbase + STAGE_FLOATS * 4 };
    unsigned bsb[2] = { smbase + AS_FLOATS * 4, smbase + (STAGE_FLOATS + AS_FLOATS) * 4 };

    int aR = t >> 3;          // 0..31 (+32j)
    int aC = (t & 7) * 4;
    int bR = t >> 5;          // 0..7  (+8j)
    int bC = (t & 31) * 4;

    int sub = lane >> 3, li = lane & 7;
    int lrow = wm + ((sub & 1) << 3) + li;
    int lcol = (sub & 2) ? 4 : 0;

    int NIT = K / GBK;

    #define ISSUE_STAGE(s, k0)                                                      \
    {                                                                               \
        unsigned as_ = asb[s], bs_ = bsb[s];                                        \
        _Pragma("unroll")                                                           \
        for (int j = 0; j < 4; j++) {                                               \
            int r = aR + 32 * j;                                                    \
            int gr = rb + r;                                                        \
            int sz = (gr < N) ? 16 : 0;                                             \
            const float* g = A + (size_t)(gr < N ? gr : 0) * K + (k0) + aC;         \
            unsigned d = as_ + (unsigned)(r * AP + aC) * 4u;                        \
            asm volatile("cp.async.cg.shared.global [%0], [%1], 16, %2;\n"          \
                         :: "r"(d), "l"(g), "r"(sz));                               \
        }                                                                           \
        _Pragma("unroll")                                                           \
        for (int j = 0; j < 4; j++) {                                               \
            int r = bR + 8 * j;                                                     \
            const float* g = B + (size_t)((k0) + r) * M + cb + bC;                  \
            unsigned d = bs_ + (unsigned)(r * BP + bC) * 4u;                        \
            asm volatile("cp.async.cg.shared.global [%0], [%1], 16;\n"              \
                         :: "r"(d), "l"(g));                                        \
        }                                                                           \
        asm volatile("cp.async.commit_group;\n");                                   \
    }

    ISSUE_STAGE(0, 0);

    for (int it = 0; it < NIT; it++) {
        int cur = it & 1;
        asm volatile("cp.async.wait_group 0;\n");
        __syncthreads();
        if (it + 1 < NIT) ISSUE_STAGE(cur ^ 1, (it + 1) * GBK);

        unsigned as_ = asb[cur], bs_ = bsb[cur];
        unsigned abase = as_ + (unsigned)(lrow * AP + lcol) * 4u;
        #pragma unroll
        for (int ks = 0; ks < 4; ks++) {
            int kk = ks * 8;
            unsigned a[4][4];
            #pragma unroll
            for (int mt = 0; mt < 4; mt++) {
                unsigned addr = abase + (unsigned)(mt * 16 * AP + kk) * 4u;
                asm volatile(
                    "ldmatrix.sync.aligned.m8n8.x4.shared.b16 {%0,%1,%2,%3}, [%4];\n"
                    : "=r"(a[mt][0]), "=r"(a[mt][1]), "=r"(a[mt][2]), "=r"(a[mt][3])
                    : "r"(addr));
            }
            #pragma unroll
            for (int mt = 0; mt < 4; mt++)
                #pragma unroll
                for (int j = 0; j < 4; j++)
                    asm volatile("cvt.rna.tf32.f32 %0, %0;\n" : "+r"(a[mt][j]));
            unsigned b[4][2];
            #pragma unroll
            for (int nt = 0; nt < 4; nt++) {
                int cc = wn + nt * 8 + grp;
                float b0, b1;
                unsigned ad0 = bs_ + (unsigned)((kk + qr) * BP + cc) * 4u;
                unsigned ad1 = bs_ + (unsigned)((kk + qr + 4) * BP + cc) * 4u;
                asm volatile("ld.shared.f32 %0, [%1];\n" : "=f"(b0) : "r"(ad0));
                asm volatile("ld.shared.f32 %0, [%1];\n" : "=f"(b1) : "r"(ad1));
                b[nt][0] = __float_as_uint(b0);
                b[nt][1] = __float_as_uint(b1);
                asm volatile("cvt.rna.tf32.f32 %0, %0;\n" : "+r"(b[nt][0]));
                asm volatile("cvt.rna.tf32.f32 %0, %0;\n" : "+r"(b[nt][1]));
            }
            #pragma unroll
            for (int mt = 0; mt < 4; mt++)
                #pragma unroll
                for (int nt = 0; nt < 4; nt++) {
                    asm volatile(
                        "mma.sync.aligned.m16n8k8.row.col.f32.tf32.tf32.f32 "
                        "{%0,%1,%2,%3}, {%4,%5,%6,%7}, {%8,%9}, {%0,%1,%2,%3};\n"
                        : "+f"(acc[mt][nt][0]), "+f"(acc[mt][nt][1]),
                          "+f"(acc[mt][nt][2]), "+f"(acc[mt][nt][3])
                        : "r"(a[mt][0]), "r"(a[mt][1]), "r"(a[mt][2]), "r"(a[mt][3]),
                          "r"(b[nt][0]), "r"(b[nt][1]));
                }
        }
    }

    // ---- C store ----
    #pragma unroll
    for (int mt = 0; mt < 4; mt++) {
        int r0 = rb + wm + mt * 16 + grp;
        #pragma unroll
        for (int nt = 0; nt < 4; nt++) {
            int c0 = cb + wn + nt * 8 + qr * 2;
            if (r0 < N)
                *(float2*)(C + (size_t)r0 * M + c0) =
                    make_float2(acc[mt][nt][0], acc[mt][nt][1]);
            if (r0 + 8 < N)
                *(float2*)(C + (size_t)(r0 + 8) * M + c0) =
                    make_float2(acc[mt][nt][2], acc[mt][nt][3]);
        }
    }

    // ---- fused attention logits ----
    if (al != nullptr) {
        const float* alh = al + blockIdx.x * DIM;
        const float* arh = ar + blockIdx.x * DIM;
        float alv[4][2], arv[4][2];
        #pragma unroll
        for (int nt = 0; nt < 4; nt++)
            #pragma unroll
            for (int c = 0; c < 2; c++) {
                int col = wn + nt * 8 + qr * 2 + c;
                alv[nt][c] = alh[col];
                arv[nt][c] = arh[col];
            }
        float pel[4][2], per_[4][2];
        #pragma unroll
        for (int mt = 0; mt < 4; mt++)
            #pragma unroll
            for (int rh = 0; rh < 2; rh++) {
                float se = 0.f, sr = 0.f;
                #pragma unroll
                for (int nt = 0; nt < 4; nt++)
                    #pragma unroll
                    for (int c = 0; c < 2; c++) {
                        float v = acc[mt][nt][rh * 2 + c];
                        se += v * alv[nt][c];
                        sr += v * arv[nt][c];
                    }
                pel[mt][rh] = se;
                per_[mt][rh] = sr;
            }
        #pragma unroll
        for (int mt = 0; mt < 4; mt++)
            #pragma unroll
            for (int rh = 0; rh < 2; rh++) {
                #pragma unroll
                for (int o = 1; o <= 2; o <<= 1) {
                    pel[mt][rh] += __shfl_xor_sync(0xffffffffu, pel[mt][rh], o);
                    per_[mt][rh] += __shfl_xor_sync(0xffffffffu, per_[mt][rh], o);
                }
            }
        __syncthreads();   // stage smem no longer needed; reuse as reduce buffer
        float* elbuf = sm;          // [128][4]
        float* erbuf = sm + 512;    // [128][4]
        if (qr == 0) {
            #pragma unroll
            for (int mt = 0; mt < 4; mt++)
                #pragma unroll
                for (int rh = 0; rh < 2; rh++) {
                    int row = wm + mt * 16 + grp + rh * 8;
                    elbuf[row * 4 + wn_idx] = pel[mt][rh];
                    erbuf[row * 4 + wn_idx] = per_[mt][rh];
                }
        }
        __syncthreads();
        if (t < 128) {
            int row = t;
            float se = elbuf[row * 4] + elbuf[row * 4 + 1] +
                       elbuf[row * 4 + 2] + elbuf[row * 4 + 3];
            float sr = erbuf[row * 4] + erbuf[row * 4 + 1] +
                       erbuf[row * 4 + 2] + erbuf[row * 4 + 3];
            if (rb + row < N) {
                elO[(size_t)(rb + row) * H + blockIdx.x] = se;
                erO[(size_t)(rb + row) * H + blockIdx.x] = sr;
            }
        }
    }
}

// ---------------- per-(dst,head) softmax weights ----------------------------
__global__ void k_alpha(const float* __restrict__ el, const float* __restrict__ er,
                        const int* __restrict__ ssrc, const int* __restrict__ off,
                        float* __restrict__ alpha, int H) {
    int idx = blockIdx.x * blockDim.x + threadIdx.x;
    if (idx >= N_NODES * H) return;
    int n = idx / H, h = idx - n * H;
    int beg = off[n], end = off[n + 1];
    float er_nh = er[n * H + h];
    float m = -INFINITY;
    for (int i = beg; i < end; i++) {
        float x = el[ssrc[i] * H + h] + er_nh;
        x = (x > 0.f) ? x : 0.2f * x;     // leaky_relu 0.2
        alpha[(size_t)i * H + h] = x;
        m = fmaxf(m, x);
    }
    float s = 0.f;
    for (int i = beg; i < end; i++) {
        float p = __expf(alpha[(size_t)i * H + h] - m);
        alpha[(size_t)i * H + h] = p;
        s += p;
    }
    float inv = 1.f / fmaxf(s, 1e-9f);
    for (int i = beg; i < end; i++)
        alpha[(size_t)i * H + h] *= inv;
}

// ---------------- weighted gather-aggregate (float4), layers 0/1 ------------
__global__ void k_aggregate(const float4* __restrict__ feat4,
                            const int* __restrict__ ssrc,
                            const int* __restrict__ off,
                            const float* __restrict__ alpha,
                            const float4* __restrict__ res4,
                            const float4* __restrict__ bias4,
                            float4* __restrict__ out4, int H, int act) {
    int n = blockIdx.x;
    int tid = threadIdx.x;        // h*32 + d4
    int h = tid >> 5;
    int HD4 = H * 32;
    int beg = off[n], end = off[n + 1];
    float4 acc = make_float4(0.f, 0.f, 0.f, 0.f);
    for (int i = beg; i < end; i++) {
        int sn = ssrc[i];
        float w = alpha[(size_t)i * H + h];
        float4 f = feat4[(size_t)sn * HD4 + tid];
        acc.x += w * f.x; acc.y += w * f.y;
        acc.z += w * f.z; acc.w += w * f.w;
    }
    if (res4 != nullptr) {
        float4 r = res4[(size_t)n * HD4 + tid];
        acc.x += r.x; acc.y += r.y; acc.z += r.z; acc.w += r.w;
    }
    float4 b = bias4[tid];
    acc.x += b.x; acc.y += b.y; acc.z += b.z; acc.w += b.w;
    if (act) {
        acc.x = (acc.x > 0.f) ? acc.x : expm1f(acc.x);
        acc.y = (acc.y > 0.f) ? acc.y : expm1f(acc.y);
        acc.z = (acc.z > 0.f) ? acc.z : expm1f(acc.z);
        acc.w = (acc.w > 0.f) ? acc.w : expm1f(acc.w);
    }
    out4[(size_t)n * HD4 + tid] = acc;
}

// ---------------- layer-2 aggregate fused with head-mean + graph pooling ----
__global__ void k_agg2_pool(const float4* __restrict__ feat4,
                            const int* __restrict__ ssrc,
                            const int* __restrict__ off,
                            const float* __restrict__ alpha,
                            const float4* __restrict__ res4,
                            const float4* __restrict__ bias4,
                            const int* __restrict__ gid,
                            float4* __restrict__ local4,
                            float* gsum, int* gcnt) {
    __shared__ float4 sh[192];
    int n = blockIdx.x;
    int tid = threadIdx.x;        // 192 = 6 heads * 32
    int h = tid >> 5;
    const int H = 6, HD4 = 192;
    int beg = off[n], end = off[n + 1];
    float4 acc = make_float4(0.f, 0.f, 0.f, 0.f);
    for (int i = beg; i < end; i++) {
        int sn = ssrc[i];
        float w = alpha[(size_t)i * H + h];
        float4 f = feat4[(size_t)sn * HD4 + tid];
        acc.x += w * f.x; acc.y += w * f.y;
        acc.z += w * f.z; acc.w += w * f.w;
    }
    float4 r = res4[(size_t)n * HD4 + tid];
    float4 b = bias4[tid];
    acc.x += r.x + b.x; acc.y += r.y + b.y;
    acc.z += r.z + b.z; acc.w += r.w + b.w;
    sh[tid] = acc;
    __syncthreads();
    if (tid < 32) {
        float4 s = sh[tid];
        #pragma unroll
        for (int hh = 1; hh < 6; hh++) {
            float4 v = sh[hh * 32 + tid];
            s.x += v.x; s.y += v.y; s.z += v.z; s.w += v.w;
        }
        const float inv6 = 1.f / 6.f;
        s.x *= inv6; s.y *= inv6; s.z *= inv6; s.w *= inv6;
        local4[(size_t)n * 32 + tid] = s;
        int g = gid[n];
        float* gs = gsum + g * DIM + tid * 4;
        atomicAdd(gs + 0, s.x); atomicAdd(gs + 1, s.y);
        atomicAdd(gs + 2, s.z); atomicAdd(gs + 3, s.w);
        if (tid == 0) atomicAdd(&gcnt[g], 1);
    }
}

__global__ void k_global_fc(const float* __restrict__ gsum, const int* __restrict__ gcnt,
                            const float* __restrict__ Wm, const float* __restrict__ bm,
                            float* __restrict__ out) {
    int g = blockIdx.x;
    int m = threadIdx.x;
    __shared__ float p[DIM];
    float c = fmaxf((float)gcnt[g], 1.f);
    p[m] = gsum[g * DIM + m] / c;
    __syncthreads();
    float acc = bm[m];
    #pragma unroll
    for (int d = 0; d < DIM; d++) acc += p[d] * Wm[d * DIM + m];
    out[(size_t)g * DIM + m] = acc;
}

// ---------------- launch ----------------------------------------------------
extern "C" void kernel_launch(void* const* d_in, const int* in_sizes, int n_in,
                              void* d_out, int out_size) {
    const float* h    = (const float*)d_in[0];
    const int*   src  = (const int*)d_in[2];
    const int*   dst  = (const int*)d_in[3];
    const int*   gid  = (const int*)d_in[4];
    const float* W0   = (const float*)d_in[5];
    const float* al0  = (const float*)d_in[6];
    const float* ar0  = (const float*)d_in[7];
    const float* b0   = (const float*)d_in[8];
    const float* W1   = (const float*)d_in[9];
    const float* al1  = (const float*)d_in[10];
    const float* ar1  = (const float*)d_in[11];
    const float* b1   = (const float*)d_in[12];
    const float* W2   = (const float*)d_in[13];
    const float* al2  = (const float*)d_in[14];
    const float* ar2  = (const float*)d_in[15];
    const float* b2   = (const float*)d_in[16];
    const float* resW2= (const float*)d_in[17];
    const float* Wm   = (const float*)d_in[18];
    const float* bm   = (const float*)d_in[19];
    float* out = (float*)d_out;

    static int smem_set = 0;
    if (!smem_set) {
        cudaFuncSetAttribute(k_tf32gemm, cudaFuncAttributeMaxDynamicSharedMemorySize,
                             GEMM_SMEM);
        smem_set = 1;
    }

    void *pfeat, *px1, *px2, *pres, *pel, *per, *palpha, *pcounts, *poff,
         *pcursor, *pssrc, *pgsum, *pgcnt;
    cudaGetSymbolAddress(&pfeat, g_feat);
    cudaGetSymbolAddress(&px1, g_x1);
    cudaGetSymbolAddress(&px2, g_x2);
    cudaGetSymbolAddress(&pres, g_res);
    cudaGetSymbolAddress(&pel, g_el);
    cudaGetSymbolAddress(&per, g_er);
    cudaGetSymbolAddress(&palpha, g_alpha);
    cudaGetSymbolAddress(&pcounts, g_counts);
    cudaGetSymbolAddress(&poff, g_off);
    cudaGetSymbolAddress(&pcursor, g_cursor);
    cudaGetSymbolAddress(&pssrc, g_ssrc);
    cudaGetSymbolAddress(&pgsum, g_gsum);
    cudaGetSymbolAddress(&pgcnt, g_gcnt);
    float* feat = (float*)pfeat;
    float* x1 = (float*)px1;
    float* x2 = (float*)px2;
    float* res = (float*)pres;
    float* el = (float*)pel;
    float* er = (float*)per;
    float* alpha = (float*)palpha;
    int* counts = (int*)pcounts;
    int* off = (int*)poff;
    int* cursor = (int*)pcursor;
    int* ssrc = (int*)pssrc;
    float* gsum = (float*)pgsum;
    int* gcnt = (int*)pgcnt;

    const int N = N_NODES, E = N_EDGES;
    dim3 gemmBlk(256);
    int gy = (N + GBM - 1) / GBM;

    // ---- CSR build, with L0 GEMM as 4th launch (profiled slot) ----
    k_zero_int<<<(N + 255) / 256, 256>>>(counts, N);
    k_count<<<(E + 255) / 256, 256>>>(dst, counts, E);
    k_scan<<<1, 1024>>>(counts, off, cursor, N);
    k_tf32gemm<<<dim3(4, gy), gemmBlk, GEMM_SMEM>>>(h, W0, feat, N, 128, 512,
                                                    al0, ar0, el, er, 4);
    k_fill<<<(E + 255) / 256, 256>>>(dst, src, cursor, ssrc, E);
    k_zero_float<<<(N_GRAPHS * DIM + 255) / 256, 256>>>(gsum, N_GRAPHS * DIM);
    k_zero_int<<<1, 64>>>(gcnt, N_GRAPHS);

    // ---- layer 0: H=4, no residual, elu ----
    k_alpha<<<(N * 4 + 255) / 256, 256>>>(el, er, ssrc, off, alpha, 4);
    k_aggregate<<<N, 128>>>((const float4*)feat, ssrc, off, alpha,
        nullptr, (const float4*)b0, (float4*)x1, 4, 1);

    // ---- layer 1: H=4, identity residual, elu ----
    k_tf32gemm<<<dim3(4, gy), gemmBlk, GEMM_SMEM>>>(x1, W1, feat, N, 512, 512,
                                                    al1, ar1, el, er, 4);
    k_alpha<<<(N * 4 + 255) / 256, 256>>>(el, er, ssrc, off, alpha, 4);
    k_aggregate<<<N, 128>>>((const float4*)feat, ssrc, off, alpha,
        (const float4*)x1, (const float4*)b1, (float4*)x2, 4, 1);

    // ---- layer 2: H=6, linear residual, fused pool ----
    k_tf32gemm<<<dim3(6, gy), gemmBlk, GEMM_SMEM>>>(x2, W2, feat, N, 512, 768,
                                                    al2, ar2, el, er, 6);
    k_tf32gemm<<<dim3(6, gy), gemmBlk, GEMM_SMEM>>>(x2, resW2, res, N, 512, 768,
                                                    nullptr, nullptr, nullptr, nullptr, 6);
    k_alpha<<<(N * 6 + 255) / 256, 256>>>(el, er, ssrc, off, alpha, 6);
    k_agg2_pool<<<N, 192>>>((const float4*)feat, ssrc, off, alpha,
        (const float4*)res, (const float4*)b2, gid, (float4*)out, gsum, gcnt);

    k_global_fc<<<N_GRAPHS, DIM>>>(gsum, gcnt, Wm, bm, out + (size_t)N * DIM);
}

// round 9
// speedup vs baseline: 1.3242x; 1.2956x over previous
#include <cuda_runtime.h>
#include <cuda_fp16.h>
#include <math.h>

#define N_NODES 20000
#define N_EDGES 320000
#define N_GRAPHS 64
#define DIM 128

// ---------------- scratch (device globals; no allocation allowed) ----------
__device__ float  g_feat[N_NODES * 768];   // per-layer fc output [N, H*D]
__device__ float  g_x1[N_NODES * 512];     // layer0 output (fp32, residual use)
__device__ float  g_x2[N_NODES * 512];     // layer1 output
__device__ float  g_res[N_NODES * 768];    // layer2 linear residual
__device__ float  g_x3[N_NODES * 768];     // layer2 output
__device__ float  g_el[N_NODES * 6];
__device__ float  g_er[N_NODES * 6];
__device__ float  g_alpha[N_EDGES * 6];
__device__ int    g_counts[N_NODES];
__device__ int    g_off[N_NODES + 1];
__device__ int    g_cursor[N_NODES];
__device__ int    g_ssrc[N_EDGES];
__device__ float  g_gsum[N_GRAPHS * DIM];
__device__ int    g_gcnt[N_GRAPHS];
__device__ __half g_h16[N_NODES * 128];    // fp16 activations for GEMM A
__device__ __half g_x1h[N_NODES * 512];
__device__ __half g_x2h[N_NODES * 512];
__device__ __half g_wt16[1114112];         // fp16 transposed weights W0t|W1t|W2t|rW2t

// ---------------- small utility kernels ------------------------------------
__global__ void k_zero_int(int* p, int n) {
    int i = blockIdx.x * blockDim.x + threadIdx.x;
    if (i < n) p[i] = 0;
}
__global__ void k_zero_float(float* p, int n) {
    int i = blockIdx.x * blockDim.x + threadIdx.x;
    if (i < n) p[i] = 0.f;
}
// fp32 -> fp16 elementwise (vectorized by 4)
__global__ void k_f2h(const float4* __restrict__ in, __half* __restrict__ out, int n4) {
    int i = blockIdx.x * blockDim.x + threadIdx.x;
    if (i < n4) {
        float4 v = in[i];
        __half2 p0 = __floats2half2_rn(v.x, v.y);
        __half2 p1 = __floats2half2_rn(v.z, v.w);
        uint2 u;
        u.x = *(unsigned*)&p0; u.y = *(unsigned*)&p1;
        ((uint2*)out)[i] = u;
    }
}
// Wt[m][k] = half(W[k][m]); W is [K,M] fp32 row-major
__global__ void k_w2h_t(const float* __restrict__ W, __half* __restrict__ Wt,
                        int K, int M) {
    __shared__ float tile[32][33];
    int mb = blockIdx.x * 32, kb = blockIdx.y * 32;
    int tx = threadIdx.x, ty = threadIdx.y;   // 32 x 8
    #pragma unroll
    for (int j = 0; j < 32; j += 8)
        tile[ty + j][tx] = W[(size_t)(kb + ty + j) * M + mb + tx];
    __syncthreads();
    #pragma unroll
    for (int j = 0; j < 32; j += 8)
        Wt[(size_t)(mb + ty + j) * K + kb + tx] = __float2half_rn(tile[tx][ty + j]);
}
__global__ void k_count(const int* __restrict__ dst, int* counts, int E) {
    int e = blockIdx.x * blockDim.x + threadIdx.x;
    if (e < E) atomicAdd(&counts[dst[e]], 1);
}
__global__ void k_scan(const int* __restrict__ counts, int* off, int* cursor, int n) {
    __shared__ int warp_sums[32];
    __shared__ int carry_s;
    int t = threadIdx.x, lane = t & 31, w = t >> 5;
    if (t == 0) { carry_s = 0; off[0] = 0; }
    __syncthreads();
    for (int base = 0; base < n; base += 1024) {
        int v = (base + t < n) ? counts[base + t] : 0;
        int x = v;
        #pragma unroll
        for (int o = 1; o < 32; o <<= 1) {
            int y = __shfl_up_sync(0xffffffffu, x, o);
            if (lane >= o) x += y;
        }
        if (lane == 31) warp_sums[w] = x;
        __syncthreads();
        if (w == 0) {
            int s = warp_sums[lane];
            #pragma unroll
            for (int o = 1; o < 32; o <<= 1) {
                int y = __shfl_up_sync(0xffffffffu, s, o);
                if (lane >= o) s += y;
            }
            warp_sums[lane] = s;
        }
        __syncthreads();
        int pre = (w > 0) ? warp_sums[w - 1] : 0;
        int incl = x + pre + carry_s;
        if (base + t < n) {
            off[base + t + 1] = incl;
            cursor[base + t] = incl - v;
        }
        __syncthreads();
        if (t == 0) carry_s += warp_sums[31];
        __syncthreads();
    }
}
__global__ void k_fill(const int* __restrict__ dst, const int* __restrict__ src,
                       int* cursor, int* ssrc, int E) {
    int e = blockIdx.x * blockDim.x + threadIdx.x;
    if (e < E) {
        int pos = atomicAdd(&cursor[dst[e]], 1);
        ssrc[pos] = src[e];
    }
}

// ---------------- FP16 tensor-core GEMM: C[N,M] = A[N,K] @ Bt[M,K]^T --------
// A fp16 [N,K] row-major; Bt fp16 [M,K] row-major (pre-transposed weights).
// fp32 accumulate via mma.m16n8k16. 128x128x32 tile, 2-stage cp.async.
#define GBM 128
#define GBN 128
#define GBK 32
#define PH 40                                // smem pitch in halfs (80 B)
#define TILE_BYTES (128 * PH * 2)            // 10240 per operand
#define STAGE_BYTES (2 * TILE_BYTES)         // 20480
#define GEMM_SMEM (2 * STAGE_BYTES)          // 40960 (< 48K default)

__global__ __launch_bounds__(256)
void k_h16gemm(const __half* __restrict__ A, const __half* __restrict__ Bt,
               float* __restrict__ C, int N, int K, int M) {
    extern __shared__ char smc[];
    int t = threadIdx.x;
    int warp = t >> 5, lane = t & 31;
    int grp = lane >> 2;   // 0..7
    int qr  = lane & 3;    // 0..3
    int wm = (warp >> 2) * 64;   // 2x4 warp grid -> 64x32 warp tiles
    int wn = (warp & 3) * 32;
    int rb = blockIdx.y * GBM;
    int cb = blockIdx.x * GBN;

    float acc[4][4][4];
    #pragma unroll
    for (int i = 0; i < 4; i++)
        #pragma unroll
        for (int j = 0; j < 4; j++)
            #pragma unroll
            for (int k = 0; k < 4; k++) acc[i][j][k] = 0.f;

    unsigned smbase = (unsigned)__cvta_generic_to_shared(smc);
    unsigned asb[2] = { smbase, smbase + STAGE_BYTES };
    unsigned bsb[2] = { smbase + TILE_BYTES, smbase + STAGE_BYTES + TILE_BYTES };

    // cp.async: 128 rows x 64B per operand = 512 x 16B chunks; 2 per thread
    // ldmatrix A addressing: lane -> row (lane&15), k8-group (lane>>4)
    int lml = lane & 15, lmh = lane >> 4;

    int NIT = K / GBK;

    #define ISSUE_STAGE(s, k0)                                                      \
    {                                                                               \
        unsigned as_ = asb[s], bs_ = bsb[s];                                        \
        _Pragma("unroll")                                                           \
        for (int j = 0; j < 2; j++) {                                               \
            int id = t + 256 * j;                                                   \
            int row = id >> 2; int c8 = (id & 3) * 8;                               \
            int gr = rb + row; int sz = (gr < N) ? 16 : 0;                          \
            const __half* g = A + (size_t)(gr < N ? gr : 0) * K + (k0) + c8;        \
            unsigned d = as_ + (unsigned)(row * PH + c8) * 2u;                      \
            asm volatile("cp.async.cg.shared.global [%0], [%1], 16, %2;\n"          \
                         :: "r"(d), "l"(g), "r"(sz));                               \
        }                                                                           \
        _Pragma("unroll")                                                           \
        for (int j = 0; j < 2; j++) {                                               \
            int id = t + 256 * j;                                                   \
            int row = id >> 2; int c8 = (id & 3) * 8;                               \
            const __half* g = Bt + (size_t)(cb + row) * K + (k0) + c8;              \
            unsigned d = bs_ + (unsigned)(row * PH + c8) * 2u;                      \
            asm volatile("cp.async.cg.shared.global [%0], [%1], 16;\n"              \
                         :: "r"(d), "l"(g));                                        \
        }                                                                           \
        asm volatile("cp.async.commit_group;\n");                                   \
    }

    ISSUE_STAGE(0, 0);

    for (int it = 0; it < NIT; it++) {
        int cur = it & 1;
        asm volatile("cp.async.wait_group 0;\n");
        __syncthreads();
        if (it + 1 < NIT) ISSUE_STAGE(cur ^ 1, (it + 1) * GBK);

        unsigned as_ = asb[cur], bs_ = bsb[cur];
        #pragma unroll
        for (int ks = 0; ks < 2; ks++) {        // k16 steps within BK=32
            int kh = ks * 16;
            unsigned a[4][4];
            #pragma unroll
            for (int mt = 0; mt < 4; mt++) {
                unsigned addr = as_ +
                    (unsigned)((wm + mt * 16 + lml) * PH + kh + lmh * 8) * 2u;
                asm volatile(
                    "ldmatrix.sync.aligned.m8n8.x4.shared.b16 {%0,%1,%2,%3}, [%4];\n"
                    : "=r"(a[mt][0]), "=r"(a[mt][1]), "=r"(a[mt][2]), "=r"(a[mt][3])
                    : "r"(addr));
            }
            unsigned b[4][2];
            #pragma unroll
            for (int nt = 0; nt < 4; nt++) {
                int cc = wn + nt * 8 + grp;
                unsigned ad0 = bs_ + (unsigned)(cc * PH + kh + 2 * qr) * 2u;
                asm volatile("ld.shared.b32 %0, [%1];\n" : "=r"(b[nt][0]) : "r"(ad0));
                asm volatile("ld.shared.b32 %0, [%1];\n" : "=r"(b[nt][1]) : "r"(ad0 + 16));
            }
            #pragma unroll
            for (int mt = 0; mt < 4; mt++)
                #pragma unroll
                for (int nt = 0; nt < 4; nt++) {
                    asm volatile(
                        "mma.sync.aligned.m16n8k16.row.col.f32.f16.f16.f32 "
                        "{%0,%1,%2,%3}, {%4,%5,%6,%7}, {%8,%9}, {%0,%1,%2,%3};\n"
                        : "+f"(acc[mt][nt][0]), "+f"(acc[mt][nt][1]),
                          "+f"(acc[mt][nt][2]), "+f"(acc[mt][nt][3])
                        : "r"(a[mt][0]), "r"(a[mt][1]), "r"(a[mt][2]), "r"(a[mt][3]),
                          "r"(b[nt][0]), "r"(b[nt][1]));
                }
        }
    }

    #pragma unroll
    for (int mt = 0; mt < 4; mt++) {
        int r0 = rb + wm + mt * 16 + grp;
        #pragma unroll
        for (int nt = 0; nt < 4; nt++) {
            int c0 = cb + wn + nt * 8 + qr * 2;
            if (r0 < N)
                *(float2*)(C + (size_t)r0 * M + c0) =
                    make_float2(acc[mt][nt][0], acc[mt][nt][1]);
            if (r0 + 8 < N)
                *(float2*)(C + (size_t)(r0 + 8) * M + c0) =
                    make_float2(acc[mt][nt][2], acc[mt][nt][3]);
        }
    }
}

// ---------------- attention logits: el/er [N,H] (float4) --------------------
__global__ void k_logits(const float4* __restrict__ feat4,
                         const float4* __restrict__ al4, const float4* __restrict__ ar4,
                         float* __restrict__ el, float* __restrict__ er, int H) {
    int w = (blockIdx.x * blockDim.x + threadIdx.x) >> 5;
    int lane = threadIdx.x & 31;
    if (w >= N_NODES * H) return;
    int n = w / H, h = w - n * H;
    float4 f = feat4[(size_t)n * H * 32 + h * 32 + lane];
    float4 a = al4[h * 32 + lane];
    float4 b = ar4[h * 32 + lane];
    float sl = f.x * a.x + f.y * a.y + f.z * a.z + f.w * a.w;
    float sr = f.x * b.x + f.y * b.y + f.z * b.z + f.w * b.w;
    #pragma unroll
    for (int o = 16; o; o >>= 1) {
        sl += __shfl_down_sync(0xffffffffu, sl, o);
        sr += __shfl_down_sync(0xffffffffu, sr, o);
    }
    if (lane == 0) { el[n * H + h] = sl; er[n * H + h] = sr; }
}

// ---------------- per-(dst,head) softmax weights ----------------------------
__global__ void k_alpha(const float* __restrict__ el, const float* __restrict__ er,
                        const int* __restrict__ ssrc, const int* __restrict__ off,
                        float* __restrict__ alpha, int H) {
    int idx = blockIdx.x * blockDim.x + threadIdx.x;
    if (idx >= N_NODES * H) return;
    int n = idx / H, h = idx - n * H;
    int beg = off[n], end = off[n + 1];
    float er_nh = er[n * H + h];
    float m = -INFINITY;
    for (int i = beg; i < end; i++) {
        float x = el[ssrc[i] * H + h] + er_nh;
        x = (x > 0.f) ? x : 0.2f * x;     // leaky_relu 0.2
        alpha[(size_t)i * H + h] = x;
        m = fmaxf(m, x);
    }
    float s = 0.f;
    for (int i = beg; i < end; i++) {
        float p = __expf(alpha[(size_t)i * H + h] - m);
        alpha[(size_t)i * H + h] = p;
        s += p;
    }
    float inv = 1.f / fmaxf(s, 1e-9f);
    for (int i = beg; i < end; i++)
        alpha[(size_t)i * H + h] *= inv;
}

// ---------------- weighted gather-aggregate (float4) ------------------------
// out16 != nullptr: also emit fp16 copy (feeds next layer's GEMM A)
__global__ void k_aggregate(const float4* __restrict__ feat4,
                            const int* __restrict__ ssrc,
                            const int* __restrict__ off,
                            const float* __restrict__ alpha,
                            const float4* __restrict__ res4,
                            const float4* __restrict__ bias4,
                            float4* __restrict__ out4,
                            __half* __restrict__ out16, int H, int act) {
    int n = blockIdx.x;
    int tid = threadIdx.x;        // h*32 + d4
    int h = tid >> 5;
    int HD4 = H * 32;
    int beg = off[n], end = off[n + 1];
    float4 acc = make_float4(0.f, 0.f, 0.f, 0.f);
    for (int i = beg; i < end; i++) {
        int sn = ssrc[i];
        float w = alpha[(size_t)i * H + h];
        float4 f = feat4[(size_t)sn * HD4 + tid];
        acc.x += w * f.x; acc.y += w * f.y;
        acc.z += w * f.z; acc.w += w * f.w;
    }
    if (res4 != nullptr) {
        float4 r = res4[(size_t)n * HD4 + tid];
        acc.x += r.x; acc.y += r.y; acc.z += r.z; acc.w += r.w;
    }
    float4 b = bias4[tid];
    acc.x += b.x; acc.y += b.y; acc.z += b.z; acc.w += b.w;
    if (act) {
        acc.x = (acc.x > 0.f) ? acc.x : expm1f(acc.x);
        acc.y = (acc.y > 0.f) ? acc.y : expm1f(acc.y);
        acc.z = (acc.z > 0.f) ? acc.z : expm1f(acc.z);
        acc.w = (acc.w > 0.f) ? acc.w : expm1f(acc.w);
    }
    out4[(size_t)n * HD4 + tid] = acc;
    if (out16 != nullptr) {
        __half2 p0 = __floats2half2_rn(acc.x, acc.y);
        __half2 p1 = __floats2half2_rn(acc.z, acc.w);
        uint2 u;
        u.x = *(unsigned*)&p0; u.y = *(unsigned*)&p1;
        ((uint2*)out16)[(size_t)n * HD4 + tid] = u;
    }
}

// ---------------- head-mean + graph pooling ---------------------------------
__global__ void k_local_pool(const float* __restrict__ x3,
                             const int* __restrict__ gid,
                             float* __restrict__ local,
                             float* gsum, int* gcnt) {
    int n = blockIdx.x;
    int d = threadIdx.x;
    float v = 0.f;
    #pragma unroll
    for (int h = 0; h < 6; h++) v += x3[(size_t)n * 768 + h * DIM + d];
    v *= (1.f / 6.f);
    local[(size_t)n * DIM + d] = v;
    int g = gid[n];
    atomicAdd(&gsum[g * DIM + d], v);
    if (d == 0) atomicAdd(&gcnt[g], 1);
}

__global__ void k_global_fc(const float* __restrict__ gsum, const int* __restrict__ gcnt,
                            const float* __restrict__ Wm, const float* __restrict__ bm,
                            float* __restrict__ out) {
    int g = blockIdx.x;
    int m = threadIdx.x;
    __shared__ float p[DIM];
    float c = fmaxf((float)gcnt[g], 1.f);
    p[m] = gsum[g * DIM + m] / c;
    __syncthreads();
    float acc = bm[m];
    #pragma unroll
    for (int d = 0; d < DIM; d++) acc += p[d] * Wm[d * DIM + m];
    out[(size_t)g * DIM + m] = acc;
}

// ---------------- launch ----------------------------------------------------
extern "C" void kernel_launch(void* const* d_in, const int* in_sizes, int n_in,
                              void* d_out, int out_size) {
    const float* h    = (const float*)d_in[0];
    const int*   src  = (const int*)d_in[2];
    const int*   dst  = (const int*)d_in[3];
    const int*   gid  = (const int*)d_in[4];
    const float* W0   = (const float*)d_in[5];
    const float* al0  = (const float*)d_in[6];
    const float* ar0  = (const float*)d_in[7];
    const float* b0   = (const float*)d_in[8];
    const float* W1   = (const float*)d_in[9];
    const float* al1  = (const float*)d_in[10];
    const float* ar1  = (const float*)d_in[11];
    const float* b1   = (const float*)d_in[12];
    const float* W2   = (const float*)d_in[13];
    const float* al2  = (const float*)d_in[14];
    const float* ar2  = (const float*)d_in[15];
    const float* b2   = (const float*)d_in[16];
    const float* resW2= (const float*)d_in[17];
    const float* Wm   = (const float*)d_in[18];
    const float* bm   = (const float*)d_in[19];
    float* out = (float*)d_out;

    void *pfeat, *px1, *px2, *pres, *px3, *pel, *per, *palpha, *pcounts, *poff,
         *pcursor, *pssrc, *pgsum, *pgcnt, *ph16, *px1h, *px2h, *pwt;
    cudaGetSymbolAddress(&pfeat, g_feat);
    cudaGetSymbolAddress(&px1, g_x1);
    cudaGetSymbolAddress(&px2, g_x2);
    cudaGetSymbolAddress(&pres, g_res);
    cudaGetSymbolAddress(&px3, g_x3);
    cudaGetSymbolAddress(&pel, g_el);
    cudaGetSymbolAddress(&per, g_er);
    cudaGetSymbolAddress(&palpha, g_alpha);
    cudaGetSymbolAddress(&pcounts, g_counts);
    cudaGetSymbolAddress(&poff, g_off);
    cudaGetSymbolAddress(&pcursor, g_cursor);
    cudaGetSymbolAddress(&pssrc, g_ssrc);
    cudaGetSymbolAddress(&pgsum, g_gsum);
    cudaGetSymbolAddress(&pgcnt, g_gcnt);
    cudaGetSymbolAddress(&ph16, g_h16);
    cudaGetSymbolAddress(&px1h, g_x1h);
    cudaGetSymbolAddress(&px2h, g_x2h);
    cudaGetSymbolAddress(&pwt, g_wt16);
    float* feat = (float*)pfeat;
    float* x1 = (float*)px1;
    float* x2 = (float*)px2;
    float* res = (float*)pres;
    float* x3 = (float*)px3;
    float* el = (float*)pel;
    float* er = (float*)per;
    float* alpha = (float*)palpha;
    int* counts = (int*)pcounts;
    int* off = (int*)poff;
    int* cursor = (int*)pcursor;
    int* ssrc = (int*)pssrc;
    float* gsum = (float*)pgsum;
    int* gcnt = (int*)pgcnt;
    __half* h16 = (__half*)ph16;
    __half* x1h = (__half*)px1h;
    __half* x2h = (__half*)px2h;
    __half* wt = (__half*)pwt;

    __half* W0t = wt;                 // [512][128]
    __half* W1t = wt + 65536;         // [512][512]
    __half* W2t = wt + 327680;        // [768][512]
    __half* rW2t = wt + 720896;       // [768][512]

    const int N = N_NODES, E = N_EDGES;
    dim3 gemmBlk(256);
    dim3 tblk(32, 8);
    int gy = (N + GBM - 1) / GBM;

    // ---- prep + CSR build (L0 GEMM in the ncu-profiled slot) ----
    k_zero_int<<<(N + 255) / 256, 256>>>(counts, N);
    k_f2h<<<(N * 128 / 4 + 255) / 256, 256>>>((const float4*)h, h16, N * 128 / 4);
    k_w2h_t<<<dim3(512 / 32, 128 / 32), tblk>>>(W0, W0t, 128, 512);
    k_h16gemm<<<dim3(4, gy), gemmBlk, GEMM_SMEM>>>(h16, W0t, feat, N, 128, 512);
    k_count<<<(E + 255) / 256, 256>>>(dst, counts, E);
    k_scan<<<1, 1024>>>(counts, off, cursor, N);
    k_fill<<<(E + 255) / 256, 256>>>(dst, src, cursor, ssrc, E);
    k_w2h_t<<<dim3(512 / 32, 512 / 32), tblk>>>(W1, W1t, 512, 512);
    k_w2h_t<<<dim3(768 / 32, 512 / 32), tblk>>>(W2, W2t, 512, 768);
    k_w2h_t<<<dim3(768 / 32, 512 / 32), tblk>>>(resW2, rW2t, 512, 768);

    // ---- layer 0: H=4, no residual, elu ----
    {
        int warps = N * 4;
        k_logits<<<(warps * 32 + 255) / 256, 256>>>((const float4*)feat,
            (const float4*)al0, (const float4*)ar0, el, er, 4);
        k_alpha<<<(N * 4 + 255) / 256, 256>>>(el, er, ssrc, off, alpha, 4);
        k_aggregate<<<N, 128>>>((const float4*)feat, ssrc, off, alpha,
            nullptr, (const float4*)b0, (float4*)x1, x1h, 4, 1);
    }
    // ---- layer 1: H=4, identity residual, elu ----
    {
        k_h16gemm<<<dim3(4, gy), gemmBlk, GEMM_SMEM>>>(x1h, W1t, feat, N, 512, 512);
        int warps = N * 4;
        k_logits<<<(warps * 32 + 255) / 256, 256>>>((const float4*)feat,
            (const float4*)al1, (const float4*)ar1, el, er, 4);
        k_alpha<<<(N * 4 + 255) / 256, 256>>>(el, er, ssrc, off, alpha, 4);
        k_aggregate<<<N, 128>>>((const float4*)feat, ssrc, off, alpha,
            (const float4*)x1, (const float4*)b1, (float4*)x2, x2h, 4, 1);
    }
    // ---- layer 2: H=6, linear residual, no act ----
    {
        k_h16gemm<<<dim3(6, gy), gemmBlk, GEMM_SMEM>>>(x2h, W2t, feat, N, 512, 768);
        k_h16gemm<<<dim3(6, gy), gemmBlk, GEMM_SMEM>>>(x2h, rW2t, res, N, 512, 768);
        int warps = N * 6;
        k_logits<<<(warps * 32 + 255) / 256, 256>>>((const float4*)feat,
            (const float4*)al2, (const float4*)ar2, el, er, 6);
        k_alpha<<<(N * 6 + 255) / 256, 256>>>(el, er, ssrc, off, alpha, 6);
        k_aggregate<<<N, 192>>>((const float4*)feat, ssrc, off, alpha,
            (const float4*)res, (const float4*)b2, (float4*)x3, nullptr, 6, 0);
    }
    // ---- head mean + graph pooling + final linear ----
    k_zero_float<<<(N_GRAPHS * DIM + 255) / 256, 256>>>(gsum, N_GRAPHS * DIM);
    k_zero_int<<<1, 64>>>(gcnt, N_GRAPHS);
    k_local_pool<<<N, DIM>>>(x3, gid, out, gsum, gcnt);
    k_global_fc<<<N_GRAPHS, DIM>>>(gsum, gcnt, Wm, bm, out + (size_t)N * DIM);
}

// round 10
// speedup vs baseline: 1.3506x; 1.0200x over previous
#include <cuda_runtime.h>
#include <cuda_fp16.h>
#include <math.h>

#define N_NODES 20000
#define N_EDGES 320000
#define N_GRAPHS 64
#define DIM 128

// ---------------- scratch (device globals; no allocation allowed) ----------
__device__ float  g_feat[N_NODES * 768];   // reused as fp16 feat [N, H*D] (half the bytes)
__device__ float  g_x1[N_NODES * 512];     // layer0 output fp32 (residual use)
__device__ float  g_x2[N_NODES * 512];
__device__ float  g_res[N_NODES * 768];    // layer2 linear residual (fp32)
__device__ float  g_x3[N_NODES * 768];
__device__ float  g_el[N_NODES * 6];
__device__ float  g_er[N_NODES * 6];
__device__ float  g_alpha[N_EDGES * 6];
__device__ int    g_counts[N_NODES];
__device__ int    g_off[N_NODES + 1];
__device__ int    g_cursor[N_NODES];
__device__ int    g_ssrc[N_EDGES];
__device__ float  g_gsum[N_GRAPHS * DIM];
__device__ int    g_gcnt[N_GRAPHS];
__device__ __half g_h16[N_NODES * 128];    // fp16 activations for GEMM A
__device__ __half g_x1h[N_NODES * 512];
__device__ __half g_x2h[N_NODES * 512];
__device__ __half g_wt16[1114112];         // fp16 transposed weights W0t|W1t|W2t|rW2t

// ---------------- small utility kernels ------------------------------------
__global__ void k_zero_int(int* p, int n) {
    int i = blockIdx.x * blockDim.x + threadIdx.x;
    if (i < n) p[i] = 0;
}
__global__ void k_zero_float(float* p, int n) {
    int i = blockIdx.x * blockDim.x + threadIdx.x;
    if (i < n) p[i] = 0.f;
}
__global__ void k_f2h(const float4* __restrict__ in, __half* __restrict__ out, int n4) {
    int i = blockIdx.x * blockDim.x + threadIdx.x;
    if (i < n4) {
        float4 v = in[i];
        __half2 p0 = __floats2half2_rn(v.x, v.y);
        __half2 p1 = __floats2half2_rn(v.z, v.w);
        uint2 u;
        u.x = *(unsigned*)&p0; u.y = *(unsigned*)&p1;
        ((uint2*)out)[i] = u;
    }
}
// Wt[m][k] = half(W[k][m]); W is [K,M] fp32 row-major
__global__ void k_w2h_t(const float* __restrict__ W, __half* __restrict__ Wt,
                        int K, int M) {
    __shared__ float tile[32][33];
    int mb = blockIdx.x * 32, kb = blockIdx.y * 32;
    int tx = threadIdx.x, ty = threadIdx.y;   // 32 x 8
    #pragma unroll
    for (int j = 0; j < 32; j += 8)
        tile[ty + j][tx] = W[(size_t)(kb + ty + j) * M + mb + tx];
    __syncthreads();
    #pragma unroll
    for (int j = 0; j < 32; j += 8)
        Wt[(size_t)(mb + ty + j) * K + kb + tx] = __float2half_rn(tile[tx][ty + j]);
}
__global__ void k_count(const int* __restrict__ dst, int* counts, int E) {
    int e = blockIdx.x * blockDim.x + threadIdx.x;
    if (e < E) atomicAdd(&counts[dst[e]], 1);
}
__global__ void k_scan(const int* __restrict__ counts, int* off, int* cursor, int n) {
    __shared__ int warp_sums[32];
    __shared__ int carry_s;
    int t = threadIdx.x, lane = t & 31, w = t >> 5;
    if (t == 0) { carry_s = 0; off[0] = 0; }
    __syncthreads();
    for (int base = 0; base < n; base += 1024) {
        int v = (base + t < n) ? counts[base + t] : 0;
        int x = v;
        #pragma unroll
        for (int o = 1; o < 32; o <<= 1) {
            int y = __shfl_up_sync(0xffffffffu, x, o);
            if (lane >= o) x += y;
        }
        if (lane == 31) warp_sums[w] = x;
        __syncthreads();
        if (w == 0) {
            int s = warp_sums[lane];
            #pragma unroll
            for (int o = 1; o < 32; o <<= 1) {
                int y = __shfl_up_sync(0xffffffffu, s, o);
                if (lane >= o) s += y;
            }
            warp_sums[lane] = s;
        }
        __syncthreads();
        int pre = (w > 0) ? warp_sums[w - 1] : 0;
        int incl = x + pre + carry_s;
        if (base + t < n) {
            off[base + t + 1] = incl;
            cursor[base + t] = incl - v;
        }
        __syncthreads();
        if (t == 0) carry_s += warp_sums[31];
        __syncthreads();
    }
}
__global__ void k_fill(const int* __restrict__ dst, const int* __restrict__ src,
                       int* cursor, int* ssrc, int E) {
    int e = blockIdx.x * blockDim.x + threadIdx.x;
    if (e < E) {
        int pos = atomicAdd(&cursor[dst[e]], 1);
        ssrc[pos] = src[e];
    }
}

// ---------------- FP16 tensor-core GEMM: C = A[N,K] @ Bt[M,K]^T --------------
// A fp16 row-major; Bt fp16 row-major. fp32 accumulate via mma.m16n8k16.
// Output: C16 (fp16) and/or C32 (fp32) — either may be null.
#define GBM 128
#define GBN 128
#define GBK 32
#define PH 40                                // smem pitch in halfs (80 B)
#define TILE_BYTES (128 * PH * 2)            // 10240 per operand
#define STAGE_BYTES (2 * TILE_BYTES)         // 20480
#define GEMM_SMEM (2 * STAGE_BYTES)          // 40960

__global__ __launch_bounds__(256)
void k_h16gemm(const __half* __restrict__ A, const __half* __restrict__ Bt,
               float* __restrict__ C32, __half* __restrict__ C16,
               int N, int K, int M) {
    extern __shared__ char smc[];
    int t = threadIdx.x;
    int warp = t >> 5, lane = t & 31;
    int grp = lane >> 2;   // 0..7
    int qr  = lane & 3;    // 0..3
    int wm = (warp >> 2) * 64;
    int wn = (warp & 3) * 32;
    int rb = blockIdx.y * GBM;
    int cb = blockIdx.x * GBN;

    float acc[4][4][4];
    #pragma unroll
    for (int i = 0; i < 4; i++)
        #pragma unroll
        for (int j = 0; j < 4; j++)
            #pragma unroll
            for (int k = 0; k < 4; k++) acc[i][j][k] = 0.f;

    unsigned smbase = (unsigned)__cvta_generic_to_shared(smc);
    unsigned asb[2] = { smbase, smbase + STAGE_BYTES };
    unsigned bsb[2] = { smbase + TILE_BYTES, smbase + STAGE_BYTES + TILE_BYTES };

    int lml = lane & 15, lmh = lane >> 4;
    int NIT = K / GBK;

    #define ISSUE_STAGE(s, k0)                                                      \
    {                                                                               \
        unsigned as_ = asb[s], bs_ = bsb[s];                                        \
        _Pragma("unroll")                                                           \
        for (int j = 0; j < 2; j++) {                                               \
            int id = t + 256 * j;                                                   \
            int row = id >> 2; int c8 = (id & 3) * 8;                               \
            int gr = rb + row; int sz = (gr < N) ? 16 : 0;                          \
            const __half* g = A + (size_t)(gr < N ? gr : 0) * K + (k0) + c8;        \
            unsigned d = as_ + (unsigned)(row * PH + c8) * 2u;                      \
            asm volatile("cp.async.cg.shared.global [%0], [%1], 16, %2;\n"          \
                         :: "r"(d), "l"(g), "r"(sz));                               \
        }                                                                           \
        _Pragma("unroll")                                                           \
        for (int j = 0; j < 2; j++) {                                               \
            int id = t + 256 * j;                                                   \
            int row = id >> 2; int c8 = (id & 3) * 8;                               \
            const __half* g = Bt + (size_t)(cb + row) * K + (k0) + c8;              \
            unsigned d = bs_ + (unsigned)(row * PH + c8) * 2u;                      \
            asm volatile("cp.async.cg.shared.global [%0], [%1], 16;\n"              \
                         :: "r"(d), "l"(g));                                        \
        }                                                                           \
        asm volatile("cp.async.commit_group;\n");                                   \
    }

    ISSUE_STAGE(0, 0);

    for (int it = 0; it < NIT; it++) {
        int cur = it & 1;
        asm volatile("cp.async.wait_group 0;\n");
        __syncthreads();
        if (it + 1 < NIT) ISSUE_STAGE(cur ^ 1, (it + 1) * GBK);

        unsigned as_ = asb[cur], bs_ = bsb[cur];
        #pragma unroll
        for (int ks = 0; ks < 2; ks++) {
            int kh = ks * 16;
            unsigned a[4][4];
            #pragma unroll
            for (int mt = 0; mt < 4; mt++) {
                unsigned addr = as_ +
                    (unsigned)((wm + mt * 16 + lml) * PH + kh + lmh * 8) * 2u;
                asm volatile(
                    "ldmatrix.sync.aligned.m8n8.x4.shared.b16 {%0,%1,%2,%3}, [%4];\n"
                    : "=r"(a[mt][0]), "=r"(a[mt][1]), "=r"(a[mt][2]), "=r"(a[mt][3])
                    : "r"(addr));
            }
            unsigned b[4][2];
            #pragma unroll
            for (int nt = 0; nt < 4; nt++) {
                int cc = wn + nt * 8 + grp;
                unsigned ad0 = bs_ + (unsigned)(cc * PH + kh + 2 * qr) * 2u;
                asm volatile("ld.shared.b32 %0, [%1];\n" : "=r"(b[nt][0]) : "r"(ad0));
                asm volatile("ld.shared.b32 %0, [%1];\n" : "=r"(b[nt][1]) : "r"(ad0 + 16));
            }
            #pragma unroll
            for (int mt = 0; mt < 4; mt++)
                #pragma unroll
                for (int nt = 0; nt < 4; nt++) {
                    asm volatile(
                        "mma.sync.aligned.m16n8k16.row.col.f32.f16.f16.f32 "
                        "{%0,%1,%2,%3}, {%4,%5,%6,%7}, {%8,%9}, {%0,%1,%2,%3};\n"
                        : "+f"(acc[mt][nt][0]), "+f"(acc[mt][nt][1]),
                          "+f"(acc[mt][nt][2]), "+f"(acc[mt][nt][3])
                        : "r"(a[mt][0]), "r"(a[mt][1]), "r"(a[mt][2]), "r"(a[mt][3]),
                          "r"(b[nt][0]), "r"(b[nt][1]));
                }
        }
    }

    #pragma unroll
    for (int mt = 0; mt < 4; mt++) {
        int r0 = rb + wm + mt * 16 + grp;
        #pragma unroll
        for (int nt = 0; nt < 4; nt++) {
            int c0 = cb + wn + nt * 8 + qr * 2;
            if (C32 != nullptr) {
                if (r0 < N)
                    *(float2*)(C32 + (size_t)r0 * M + c0) =
                        make_float2(acc[mt][nt][0], acc[mt][nt][1]);
                if (r0 + 8 < N)
                    *(float2*)(C32 + (size_t)(r0 + 8) * M + c0) =
                        make_float2(acc[mt][nt][2], acc[mt][nt][3]);
            }
            if (C16 != nullptr) {
                if (r0 < N) {
                    __half2 p = __floats2half2_rn(acc[mt][nt][0], acc[mt][nt][1]);
                    *(unsigned*)(C16 + (size_t)r0 * M + c0) = *(unsigned*)&p;
                }
                if (r0 + 8 < N) {
                    __half2 p = __floats2half2_rn(acc[mt][nt][2], acc[mt][nt][3]);
                    *(unsigned*)(C16 + (size_t)(r0 + 8) * M + c0) = *(unsigned*)&p;
                }
            }
        }
    }
}

// ---------------- attention logits from fp16 feat ----------------------------
__global__ void k_logits(const uint2* __restrict__ feat16,
                         const float4* __restrict__ al4, const float4* __restrict__ ar4,
                         float* __restrict__ el, float* __restrict__ er, int H) {
    int w = (blockIdx.x * blockDim.x + threadIdx.x) >> 5;
    int lane = threadIdx.x & 31;
    if (w >= N_NODES * H) return;
    int n = w / H, h = w - n * H;
    uint2 u = feat16[(size_t)n * H * 32 + h * 32 + lane];
    float2 f0 = __half22float2(*(__half2*)&u.x);
    float2 f1 = __half22float2(*(__half2*)&u.y);
    float4 a = al4[h * 32 + lane];
    float4 b = ar4[h * 32 + lane];
    float sl = f0.x * a.x + f0.y * a.y + f1.x * a.z + f1.y * a.w;
    float sr = f0.x * b.x + f0.y * b.y + f1.x * b.z + f1.y * b.w;
    #pragma unroll
    for (int o = 16; o; o >>= 1) {
        sl += __shfl_down_sync(0xffffffffu, sl, o);
        sr += __shfl_down_sync(0xffffffffu, sr, o);
    }
    if (lane == 0) { el[n * H + h] = sl; er[n * H + h] = sr; }
}

// ---------------- per-(dst,head) softmax weights ----------------------------
__global__ void k_alpha(const float* __restrict__ el, const float* __restrict__ er,
                        const int* __restrict__ ssrc, const int* __restrict__ off,
                        float* __restrict__ alpha, int H) {
    int idx = blockIdx.x * blockDim.x + threadIdx.x;
    if (idx >= N_NODES * H) return;
    int n = idx / H, h = idx - n * H;
    int beg = off[n], end = off[n + 1];
    float er_nh = er[n * H + h];
    float m = -INFINITY;
    for (int i = beg; i < end; i++) {
        float x = el[ssrc[i] * H + h] + er_nh;
        x = (x > 0.f) ? x : 0.2f * x;     // leaky_relu 0.2
        alpha[(size_t)i * H + h] = x;
        m = fmaxf(m, x);
    }
    float s = 0.f;
    for (int i = beg; i < end; i++) {
        float p = __expf(alpha[(size_t)i * H + h] - m);
        alpha[(size_t)i * H + h] = p;
        s += p;
    }
    float inv = 1.f / fmaxf(s, 1e-9f);
    for (int i = beg; i < end; i++)
        alpha[(size_t)i * H + h] *= inv;
}

// ---------------- weighted gather-aggregate (fp16 feat) ---------------------
__global__ void k_aggregate(const uint2* __restrict__ feat16,
                            const int* __restrict__ ssrc,
                            const int* __restrict__ off,
                            const float* __restrict__ alpha,
                            const float4* __restrict__ res4,
                            const float4* __restrict__ bias4,
                            float4* __restrict__ out4,
                            __half* __restrict__ out16, int H, int act) {
    int n = blockIdx.x;
    int tid = threadIdx.x;        // h*32 + d4
    int h = tid >> 5;
    int HD4 = H * 32;
    int beg = off[n], end = off[n + 1];
    float4 acc = make_float4(0.f, 0.f, 0.f, 0.f);
    for (int i = beg; i < end; i++) {
        int sn = ssrc[i];
        float w = alpha[(size_t)i * H + h];
        uint2 u = feat16[(size_t)sn * HD4 + tid];
        float2 f0 = __half22float2(*(__half2*)&u.x);
        float2 f1 = __half22float2(*(__half2*)&u.y);
        acc.x += w * f0.x; acc.y += w * f0.y;
        acc.z += w * f1.x; acc.w += w * f1.y;
    }
    if (res4 != nullptr) {
        float4 r = res4[(size_t)n * HD4 + tid];
        acc.x += r.x; acc.y += r.y; acc.z += r.z; acc.w += r.w;
    }
    float4 b = bias4[tid];
    acc.x += b.x; acc.y += b.y; acc.z += b.z; acc.w += b.w;
    if (act) {
        acc.x = (acc.x > 0.f) ? acc.x : expm1f(acc.x);
        acc.y = (acc.y > 0.f) ? acc.y : expm1f(acc.y);
        acc.z = (acc.z > 0.f) ? acc.z : expm1f(acc.z);
        acc.w = (acc.w > 0.f) ? acc.w : expm1f(acc.w);
    }
    out4[(size_t)n * HD4 + tid] = acc;
    if (out16 != nullptr) {
        __half2 p0 = __floats2half2_rn(acc.x, acc.y);
        __half2 p1 = __floats2half2_rn(acc.z, acc.w);
        uint2 u;
        u.x = *(unsigned*)&p0; u.y = *(unsigned*)&p1;
        ((uint2*)out16)[(size_t)n * HD4 + tid] = u;
    }
}

// ---------------- head-mean + graph pooling ---------------------------------
__global__ void k_local_pool(const float* __restrict__ x3,
                             const int* __restrict__ gid,
                             float* __restrict__ local,
                             float* gsum, int* gcnt) {
    int n = blockIdx.x;
    int d = threadIdx.x;
    float v = 0.f;
    #pragma unroll
    for (int h = 0; h < 6; h++) v += x3[(size_t)n * 768 + h * DIM + d];
    v *= (1.f / 6.f);
    local[(size_t)n * DIM + d] = v;
    int g = gid[n];
    atomicAdd(&gsum[g * DIM + d], v);
    if (d == 0) atomicAdd(&gcnt[g], 1);
}

__global__ void k_global_fc(const float* __restrict__ gsum, const int* __restrict__ gcnt,
                            const float* __restrict__ Wm, const float* __restrict__ bm,
                            float* __restrict__ out) {
    int g = blockIdx.x;
    int m = threadIdx.x;
    __shared__ float p[DIM];
    float c = fmaxf((float)gcnt[g], 1.f);
    p[m] = gsum[g * DIM + m] / c;
    __syncthreads();
    float acc = bm[m];
    #pragma unroll
    for (int d = 0; d < DIM; d++) acc += p[d] * Wm[d * DIM + m];
    out[(size_t)g * DIM + m] = acc;
}

// ---------------- launch ----------------------------------------------------
extern "C" void kernel_launch(void* const* d_in, const int* in_sizes, int n_in,
                              void* d_out, int out_size) {
    const float* h    = (const float*)d_in[0];
    const int*   src  = (const int*)d_in[2];
    const int*   dst  = (const int*)d_in[3];
    const int*   gid  = (const int*)d_in[4];
    const float* W0   = (const float*)d_in[5];
    const float* al0  = (const float*)d_in[6];
    const float* ar0  = (const float*)d_in[7];
    const float* b0   = (const float*)d_in[8];
    const float* W1   = (const float*)d_in[9];
    const float* al1  = (const float*)d_in[10];
    const float* ar1  = (const float*)d_in[11];
    const float* b1   = (const float*)d_in[12];
    const float* W2   = (const float*)d_in[13];
    const float* al2  = (const float*)d_in[14];
    const float* ar2  = (const float*)d_in[15];
    const float* b2   = (const float*)d_in[16];
    const float* resW2= (const float*)d_in[17];
    const float* Wm   = (const float*)d_in[18];
    const float* bm   = (const float*)d_in[19];
    float* out = (float*)d_out;

    void *pfeat, *px1, *px2, *pres, *px3, *pel, *per, *palpha, *pcounts, *poff,
         *pcursor, *pssrc, *pgsum, *pgcnt, *ph16, *px1h, *px2h, *pwt;
    cudaGetSymbolAddress(&pfeat, g_feat);
    cudaGetSymbolAddress(&px1, g_x1);
    cudaGetSymbolAddress(&px2, g_x2);
    cudaGetSymbolAddress(&pres, g_res);
    cudaGetSymbolAddress(&px3, g_x3);
    cudaGetSymbolAddress(&pel, g_el);
    cudaGetSymbolAddress(&per, g_er);
    cudaGetSymbolAddress(&palpha, g_alpha);
    cudaGetSymbolAddress(&pcounts, g_counts);
    cudaGetSymbolAddress(&poff, g_off);
    cudaGetSymbolAddress(&pcursor, g_cursor);
    cudaGetSymbolAddress(&pssrc, g_ssrc);
    cudaGetSymbolAddress(&pgsum, g_gsum);
    cudaGetSymbolAddress(&pgcnt, g_gcnt);
    cudaGetSymbolAddress(&ph16, g_h16);
    cudaGetSymbolAddress(&px1h, g_x1h);
    cudaGetSymbolAddress(&px2h, g_x2h);
    cudaGetSymbolAddress(&pwt, g_wt16);
    __half* feat16 = (__half*)pfeat;     // fp16 view of g_feat storage
    float* x1 = (float*)px1;
    float* x2 = (float*)px2;
    float* res = (float*)pres;
    float* x3 = (float*)px3;
    float* el = (float*)pel;
    float* er = (float*)per;
    float* alpha = (float*)palpha;
    int* counts = (int*)pcounts;
    int* off = (int*)poff;
    int* cursor = (int*)pcursor;
    int* ssrc = (int*)pssrc;
    float* gsum = (float*)pgsum;
    int* gcnt = (int*)pgcnt;
    __half* h16 = (__half*)ph16;
    __half* x1h = (__half*)px1h;
    __half* x2h = (__half*)px2h;
    __half* wt = (__half*)pwt;

    __half* W0t = wt;                 // [512][128]
    __half* W1t = wt + 65536;         // [512][512]
    __half* W2t = wt + 327680;        // [768][512]
    __half* rW2t = wt + 720896;       // [768][512]

    const int N = N_NODES, E = N_EDGES;
    dim3 gemmBlk(256);
    dim3 tblk(32, 8);
    int gy = (N + GBM - 1) / GBM;

    // ---- prep + CSR build (L0 GEMM in the ncu-profiled slot) ----
    k_zero_int<<<(N + 255) / 256, 256>>>(counts, N);
    k_f2h<<<(N * 128 / 4 + 255) / 256, 256>>>((const float4*)h, h16, N * 128 / 4);
    k_w2h_t<<<dim3(512 / 32, 128 / 32), tblk>>>(W0, W0t, 128, 512);
    k_h16gemm<<<dim3(4, gy), gemmBlk, GEMM_SMEM>>>(h16, W0t, nullptr, feat16, N, 128, 512);
    k_count<<<(E + 255) / 256, 256>>>(dst, counts, E);
    k_scan<<<1, 1024>>>(counts, off, cursor, N);
    k_fill<<<(E + 255) / 256, 256>>>(dst, src, cursor, ssrc, E);
    k_w2h_t<<<dim3(512 / 32, 512 / 32), tblk>>>(W1, W1t, 512, 512);
    k_w2h_t<<<dim3(768 / 32, 512 / 32), tblk>>>(W2, W2t, 512, 768);
    k_w2h_t<<<dim3(768 / 32, 512 / 32), tblk>>>(resW2, rW2t, 512, 768);

    // ---- layer 0: H=4, no residual, elu ----
    {
        int warps = N * 4;
        k_logits<<<(warps * 32 + 255) / 256, 256>>>((const uint2*)feat16,
            (const float4*)al0, (const float4*)ar0, el, er, 4);
        k_alpha<<<(N * 4 + 255) / 256, 256>>>(el, er, ssrc, off, alpha, 4);
        k_aggregate<<<N, 128>>>((const uint2*)feat16, ssrc, off, alpha,
            nullptr, (const float4*)b0, (float4*)x1, x1h, 4, 1);
    }
    // ---- layer 1: H=4, identity residual, elu ----
    {
        k_h16gemm<<<dim3(4, gy), gemmBlk, GEMM_SMEM>>>(x1h, W1t, nullptr, feat16, N, 512, 512);
        int warps = N * 4;
        k_logits<<<(warps * 32 + 255) / 256, 256>>>((const uint2*)feat16,
            (const float4*)al1, (const float4*)ar1, el, er, 4);
        k_alpha<<<(N * 4 + 255) / 256, 256>>>(el, er, ssrc, off, alpha, 4);
        k_aggregate<<<N, 128>>>((const uint2*)feat16, ssrc, off, alpha,
            (const float4*)x1, (const float4*)b1, (float4*)x2, x2h, 4, 1);
    }
    // ---- layer 2: H=6, linear residual, no act ----
    {
        k_h16gemm<<<dim3(6, gy), gemmBlk, GEMM_SMEM>>>(x2h, W2t, nullptr, feat16, N, 512, 768);
        k_h16gemm<<<dim3(6, gy), gemmBlk, GEMM_SMEM>>>(x2h, rW2t, res, nullptr, N, 512, 768);
        int warps = N * 6;
        k_logits<<<(warps * 32 + 255) / 256, 256>>>((const uint2*)feat16,
            (const float4*)al2, (const float4*)ar2, el, er, 6);
        k_alpha<<<(N * 6 + 255) / 256, 256>>>(el, er, ssrc, off, alpha, 6);
        k_aggregate<<<N, 192>>>((const uint2*)feat16, ssrc, off, alpha,
            (const float4*)res, (const float4*)b2, (float4*)x3, nullptr, 6, 0);
    }
    // ---- head mean + graph pooling + final linear ----
    k_zero_float<<<(N_GRAPHS * DIM + 255) / 256, 256>>>(gsum, N_GRAPHS * DIM);
    k_zero_int<<<1, 64>>>(gcnt, N_GRAPHS);
    k_local_pool<<<N, DIM>>>(x3, gid, out, gsum, gcnt);
    k_global_fc<<<N_GRAPHS, DIM>>>(gsum, gcnt, Wm, bm, out + (size_t)N * DIM);
}

// round 11
// speedup vs baseline: 1.3715x; 1.0154x over previous
#include <cuda_runtime.h>
#include <cuda_fp16.h>
#include <math.h>

#define N_NODES 20000
#define N_EDGES 320000
#define N_GRAPHS 64
#define DIM 128

// ---------------- scratch (device globals; no allocation allowed) ----------
__device__ float  g_feat[N_NODES * 768];   // reused as fp16 feat [N, H*D]
__device__ float  g_x1[N_NODES * 512];     // layer0 output fp32 (residual use)
__device__ float  g_x2[N_NODES * 512];
__device__ float  g_res[N_NODES * 128];    // layer2 mean-residual (fp32) [N,128]
__device__ float  g_el[N_NODES * 6];
__device__ float  g_er[N_NODES * 6];
__device__ float  g_alpha[N_EDGES * 6];
__device__ int    g_counts[N_NODES];
__device__ int    g_off[N_NODES + 1];
__device__ int    g_cursor[N_NODES];
__device__ int    g_ssrc[N_EDGES];
__device__ float  g_gsum[N_GRAPHS * DIM];
__device__ int    g_gcnt[N_GRAPHS];
__device__ float  g_b2m[DIM];
__device__ __half g_h16[N_NODES * 128];    // fp16 activations for GEMM A
__device__ __half g_x1h[N_NODES * 512];
__device__ __half g_x2h[N_NODES * 512];
__device__ __half g_wt16[1114112];         // fp16 weights: W0t|W1t|W2t|rW2mt

// ---------------- small utility kernels ------------------------------------
__global__ void k_zero_int(int* p, int n) {
    int i = blockIdx.x * blockDim.x + threadIdx.x;
    if (i < n) p[i] = 0;
}
__global__ void k_zero_float(float* p, int n) {
    int i = blockIdx.x * blockDim.x + threadIdx.x;
    if (i < n) p[i] = 0.f;
}
__global__ void k_f2h(const float4* __restrict__ in, __half* __restrict__ out, int n4) {
    int i = blockIdx.x * blockDim.x + threadIdx.x;
    if (i < n4) {
        float4 v = in[i];
        __half2 p0 = __floats2half2_rn(v.x, v.y);
        __half2 p1 = __floats2half2_rn(v.z, v.w);
        uint2 u;
        u.x = *(unsigned*)&p0; u.y = *(unsigned*)&p1;
        ((uint2*)out)[i] = u;
    }
}
// Wt[m][k] = half(W[k][m]); W is [K,M] fp32 row-major
__global__ void k_w2h_t(const float* __restrict__ W, __half* __restrict__ Wt,
                        int K, int M) {
    __shared__ float tile[32][33];
    int mb = blockIdx.x * 32, kb = blockIdx.y * 32;
    int tx = threadIdx.x, ty = threadIdx.y;   // 32 x 8
    #pragma unroll
    for (int j = 0; j < 32; j += 8)
        tile[ty + j][tx] = W[(size_t)(kb + ty + j) * M + mb + tx];
    __syncthreads();
    #pragma unroll
    for (int j = 0; j < 32; j += 8)
        Wt[(size_t)(mb + ty + j) * K + kb + tx] = __float2half_rn(tile[tx][ty + j]);
}
// rW2mt[m][k] = half( mean_h resW2[k][h*128+m] ); resW2 is [512,768]
__global__ void k_wmean_t(const float* __restrict__ W, __half* __restrict__ Wt) {
    int idx = blockIdx.x * blockDim.x + threadIdx.x;   // 128*512
    if (idx >= 128 * 512) return;
    int m = idx >> 9, k = idx & 511;
    float s = 0.f;
    #pragma unroll
    for (int h = 0; h < 6; h++) s += W[(size_t)k * 768 + h * 128 + m];
    Wt[(size_t)m * 512 + k] = __float2half_rn(s * (1.f / 6.f));
}
__global__ void k_b2m(const float* __restrict__ b2, float* __restrict__ b2m) {
    int d = threadIdx.x;   // 128
    float s = 0.f;
    #pragma unroll
    for (int h = 0; h < 6; h++) s += b2[h * 128 + d];
    b2m[d] = s * (1.f / 6.f);
}
__global__ void k_count(const int* __restrict__ dst, int* counts, int E) {
    int e = blockIdx.x * blockDim.x + threadIdx.x;
    if (e < E) atomicAdd(&counts[dst[e]], 1);
}
__global__ void k_scan(const int* __restrict__ counts, int* off, int* cursor, int n) {
    __shared__ int warp_sums[32];
    __shared__ int carry_s;
    int t = threadIdx.x, lane = t & 31, w = t >> 5;
    if (t == 0) { carry_s = 0; off[0] = 0; }
    __syncthreads();
    for (int base = 0; base < n; base += 1024) {
        int v = (base + t < n) ? counts[base + t] : 0;
        int x = v;
        #pragma unroll
        for (int o = 1; o < 32; o <<= 1) {
            int y = __shfl_up_sync(0xffffffffu, x, o);
            if (lane >= o) x += y;
        }
        if (lane == 31) warp_sums[w] = x;
        __syncthreads();
        if (w == 0) {
            int s = warp_sums[lane];
            #pragma unroll
            for (int o = 1; o < 32; o <<= 1) {
                int y = __shfl_up_sync(0xffffffffu, s, o);
                if (lane >= o) s += y;
            }
            warp_sums[lane] = s;
        }
        __syncthreads();
        int pre = (w > 0) ? warp_sums[w - 1] : 0;
        int incl = x + pre + carry_s;
        if (base + t < n) {
            off[base + t + 1] = incl;
            cursor[base + t] = incl - v;
        }
        __syncthreads();
        if (t == 0) carry_s += warp_sums[31];
        __syncthreads();
    }
}
__global__ void k_fill(const int* __restrict__ dst, const int* __restrict__ src,
                       int* cursor, int* ssrc, int E) {
    int e = blockIdx.x * blockDim.x + threadIdx.x;
    if (e < E) {
        int pos = atomicAdd(&cursor[dst[e]], 1);
        ssrc[pos] = src[e];
    }
}

// ---------------- FP16 tensor-core GEMM: C = A[N,K] @ Bt[M,K]^T --------------
#define GBM 128
#define GBN 128
#define GBK 32
#define PH 40
#define TILE_BYTES (128 * PH * 2)
#define STAGE_BYTES (2 * TILE_BYTES)
#define GEMM_SMEM (2 * STAGE_BYTES)          // 40960

__global__ __launch_bounds__(256)
void k_h16gemm(const __half* __restrict__ A, const __half* __restrict__ Bt,
               float* __restrict__ C32, __half* __restrict__ C16,
               int N, int K, int M) {
    extern __shared__ char smc[];
    int t = threadIdx.x;
    int warp = t >> 5, lane = t & 31;
    int grp = lane >> 2;
    int qr  = lane & 3;
    int wm = (warp >> 2) * 64;
    int wn = (warp & 3) * 32;
    int rb = blockIdx.y * GBM;
    int cb = blockIdx.x * GBN;

    float acc[4][4][4];
    #pragma unroll
    for (int i = 0; i < 4; i++)
        #pragma unroll
        for (int j = 0; j < 4; j++)
            #pragma unroll
            for (int k = 0; k < 4; k++) acc[i][j][k] = 0.f;

    unsigned smbase = (unsigned)__cvta_generic_to_shared(smc);
    unsigned asb[2] = { smbase, smbase + STAGE_BYTES };
    unsigned bsb[2] = { smbase + TILE_BYTES, smbase + STAGE_BYTES + TILE_BYTES };

    int lml = lane & 15, lmh = lane >> 4;
    int NIT = K / GBK;

    #define ISSUE_STAGE(s, k0)                                                      \
    {                                                                               \
        unsigned as_ = asb[s], bs_ = bsb[s];                                        \
        _Pragma("unroll")                                                           \
        for (int j = 0; j < 2; j++) {                                               \
            int id = t + 256 * j;                                                   \
            int row = id >> 2; int c8 = (id & 3) * 8;                               \
            int gr = rb + row; int sz = (gr < N) ? 16 : 0;                          \
            const __half* g = A + (size_t)(gr < N ? gr : 0) * K + (k0) + c8;        \
            unsigned d = as_ + (unsigned)(row * PH + c8) * 2u;                      \
            asm volatile("cp.async.cg.shared.global [%0], [%1], 16, %2;\n"          \
                         :: "r"(d), "l"(g), "r"(sz));                               \
        }                                                                           \
        _Pragma("unroll")                                                           \
        for (int j = 0; j < 2; j++) {                                               \
            int id = t + 256 * j;                                                   \
            int row = id >> 2; int c8 = (id & 3) * 8;                               \
            const __half* g = Bt + (size_t)(cb + row) * K + (k0) + c8;              \
            unsigned d = bs_ + (unsigned)(row * PH + c8) * 2u;                      \
            asm volatile("cp.async.cg.shared.global [%0], [%1], 16;\n"              \
                         :: "r"(d), "l"(g));                                        \
        }                                                                           \
        asm volatile("cp.async.commit_group;\n");                                   \
    }

    ISSUE_STAGE(0, 0);

    for (int it = 0; it < NIT; it++) {
        int cur = it & 1;
        asm volatile("cp.async.wait_group 0;\n");
        __syncthreads();
        if (it + 1 < NIT) ISSUE_STAGE(cur ^ 1, (it + 1) * GBK);

        unsigned as_ = asb[cur], bs_ = bsb[cur];
        #pragma unroll
        for (int ks = 0; ks < 2; ks++) {
            int kh = ks * 16;
            unsigned a[4][4];
            #pragma unroll
            for (int mt = 0; mt < 4; mt++) {
                unsigned addr = as_ +
                    (unsigned)((wm + mt * 16 + lml) * PH + kh + lmh * 8) * 2u;
                asm volatile(
                    "ldmatrix.sync.aligned.m8n8.x4.shared.b16 {%0,%1,%2,%3}, [%4];\n"
                    : "=r"(a[mt][0]), "=r"(a[mt][1]), "=r"(a[mt][2]), "=r"(a[mt][3])
                    : "r"(addr));
            }
            unsigned b[4][2];
            #pragma unroll
            for (int nt = 0; nt < 4; nt++) {
                int cc = wn + nt * 8 + grp;
                unsigned ad0 = bs_ + (unsigned)(cc * PH + kh + 2 * qr) * 2u;
                asm volatile("ld.shared.b32 %0, [%1];\n" : "=r"(b[nt][0]) : "r"(ad0));
                asm volatile("ld.shared.b32 %0, [%1];\n" : "=r"(b[nt][1]) : "r"(ad0 + 16));
            }
            #pragma unroll
            for (int mt = 0; mt < 4; mt++)
                #pragma unroll
                for (int nt = 0; nt < 4; nt++) {
                    asm volatile(
                        "mma.sync.aligned.m16n8k16.row.col.f32.f16.f16.f32 "
                        "{%0,%1,%2,%3}, {%4,%5,%6,%7}, {%8,%9}, {%0,%1,%2,%3};\n"
                        : "+f"(acc[mt][nt][0]), "+f"(acc[mt][nt][1]),
                          "+f"(acc[mt][nt][2]), "+f"(acc[mt][nt][3])
                        : "r"(a[mt][0]), "r"(a[mt][1]), "r"(a[mt][2]), "r"(a[mt][3]),
                          "r"(b[nt][0]), "r"(b[nt][1]));
                }
        }
    }

    #pragma unroll
    for (int mt = 0; mt < 4; mt++) {
        int r0 = rb + wm + mt * 16 + grp;
        #pragma unroll
        for (int nt = 0; nt < 4; nt++) {
            int c0 = cb + wn + nt * 8 + qr * 2;
            if (C32 != nullptr) {
                if (r0 < N)
                    *(float2*)(C32 + (size_t)r0 * M + c0) =
                        make_float2(acc[mt][nt][0], acc[mt][nt][1]);
                if (r0 + 8 < N)
                    *(float2*)(C32 + (size_t)(r0 + 8) * M + c0) =
                        make_float2(acc[mt][nt][2], acc[mt][nt][3]);
            }
            if (C16 != nullptr) {
                if (r0 < N) {
                    __half2 p = __floats2half2_rn(acc[mt][nt][0], acc[mt][nt][1]);
                    *(unsigned*)(C16 + (size_t)r0 * M + c0) = *(unsigned*)&p;
                }
                if (r0 + 8 < N) {
                    __half2 p = __floats2half2_rn(acc[mt][nt][2], acc[mt][nt][3]);
                    *(unsigned*)(C16 + (size_t)(r0 + 8) * M + c0) = *(unsigned*)&p;
                }
            }
        }
    }
}

// ---------------- attention logits from fp16 feat ----------------------------
__global__ void k_logits(const uint2* __restrict__ feat16,
                         const float4* __restrict__ al4, const float4* __restrict__ ar4,
                         float* __restrict__ el, float* __restrict__ er, int H) {
    int w = (blockIdx.x * blockDim.x + threadIdx.x) >> 5;
    int lane = threadIdx.x & 31;
    if (w >= N_NODES * H) return;
    int n = w / H, h = w - n * H;
    uint2 u = feat16[(size_t)n * H * 32 + h * 32 + lane];
    float2 f0 = __half22float2(*(__half2*)&u.x);
    float2 f1 = __half22float2(*(__half2*)&u.y);
    float4 a = al4[h * 32 + lane];
    float4 b = ar4[h * 32 + lane];
    float sl = f0.x * a.x + f0.y * a.y + f1.x * a.z + f1.y * a.w;
    float sr = f0.x * b.x + f0.y * b.y + f1.x * b.z + f1.y * b.w;
    #pragma unroll
    for (int o = 16; o; o >>= 1) {
        sl += __shfl_down_sync(0xffffffffu, sl, o);
        sr += __shfl_down_sync(0xffffffffu, sr, o);
    }
    if (lane == 0) { el[n * H + h] = sl; er[n * H + h] = sr; }
}

// ---------------- per-(dst,head) softmax weights ----------------------------
__global__ void k_alpha(const float* __restrict__ el, const float* __restrict__ er,
                        const int* __restrict__ ssrc, const int* __restrict__ off,
                        float* __restrict__ alpha, int H) {
    int idx = blockIdx.x * blockDim.x + threadIdx.x;
    if (idx >= N_NODES * H) return;
    int n = idx / H, h = idx - n * H;
    int beg = off[n], end = off[n + 1];
    float er_nh = er[n * H + h];
    float m = -INFINITY;
    for (int i = beg; i < end; i++) {
        float x = el[ssrc[i] * H + h] + er_nh;
        x = (x > 0.f) ? x : 0.2f * x;     // leaky_relu 0.2
        alpha[(size_t)i * H + h] = x;
        m = fmaxf(m, x);
    }
    float s = 0.f;
    for (int i = beg; i < end; i++) {
        float p = __expf(alpha[(size_t)i * H + h] - m);
        alpha[(size_t)i * H + h] = p;
        s += p;
    }
    float inv = 1.f / fmaxf(s, 1e-9f);
    for (int i = beg; i < end; i++)
        alpha[(size_t)i * H + h] *= inv;
}

// ---------------- weighted gather-aggregate (fp16 feat), layers 0/1 ---------
__global__ void k_aggregate(const uint2* __restrict__ feat16,
                            const int* __restrict__ ssrc,
                            const int* __restrict__ off,
                            const float* __restrict__ alpha,
                            const float4* __restrict__ res4,
                            const float4* __restrict__ bias4,
                            float4* __restrict__ out4,
                            __half* __restrict__ out16, int H, int act) {
    int n = blockIdx.x;
    int tid = threadIdx.x;        // h*32 + d4
    int h = tid >> 5;
    int HD4 = H * 32;
    int beg = off[n], end = off[n + 1];
    float4 acc = make_float4(0.f, 0.f, 0.f, 0.f);
    for (int i = beg; i < end; i++) {
        int sn = ssrc[i];
        float w = alpha[(size_t)i * H + h];
        uint2 u = feat16[(size_t)sn * HD4 + tid];
        float2 f0 = __half22float2(*(__half2*)&u.x);
        float2 f1 = __half22float2(*(__half2*)&u.y);
        acc.x += w * f0.x; acc.y += w * f0.y;
        acc.z += w * f1.x; acc.w += w * f1.y;
    }
    if (res4 != nullptr) {
        float4 r = res4[(size_t)n * HD4 + tid];
        acc.x += r.x; acc.y += r.y; acc.z += r.z; acc.w += r.w;
    }
    float4 b = bias4[tid];
    acc.x += b.x; acc.y += b.y; acc.z += b.z; acc.w += b.w;
    if (act) {
        acc.x = (acc.x > 0.f) ? acc.x : expm1f(acc.x);
        acc.y = (acc.y > 0.f) ? acc.y : expm1f(acc.y);
        acc.z = (acc.z > 0.f) ? acc.z : expm1f(acc.z);
        acc.w = (acc.w > 0.f) ? acc.w : expm1f(acc.w);
    }
    out4[(size_t)n * HD4 + tid] = acc;
    if (out16 != nullptr) {
        __half2 p0 = __floats2half2_rn(acc.x, acc.y);
        __half2 p1 = __floats2half2_rn(acc.z, acc.w);
        uint2 u;
        u.x = *(unsigned*)&p0; u.y = *(unsigned*)&p1;
        ((uint2*)out16)[(size_t)n * HD4 + tid] = u;
    }
}

// ---------------- layer-2: aggregate + head-mean + resm + pool --------------
__global__ void k_agg2_pool(const uint2* __restrict__ feat16,
                            const int* __restrict__ ssrc,
                            const int* __restrict__ off,
                            const float* __restrict__ alpha,
                            const float4* __restrict__ resm4,   // [N,32] float4
                            const float* __restrict__ b2m,
                            const int* __restrict__ gid,
                            float4* __restrict__ local4,
                            float* gsum, int* gcnt) {
    __shared__ float4 sh[192];
    int n = blockIdx.x;
    int tid = threadIdx.x;        // 192 = 6 heads x 32
    int h = tid >> 5;
    const int H = 6, HD4 = 192;
    int beg = off[n], end = off[n + 1];
    float4 acc = make_float4(0.f, 0.f, 0.f, 0.f);
    for (int i = beg; i < end; i++) {
        int sn = ssrc[i];
        float w = alpha[(size_t)i * H + h];
        uint2 u = feat16[(size_t)sn * HD4 + tid];
        float2 f0 = __half22float2(*(__half2*)&u.x);
        float2 f1 = __half22float2(*(__half2*)&u.y);
        acc.x += w * f0.x; acc.y += w * f0.y;
        acc.z += w * f1.x; acc.w += w * f1.y;
    }
    sh[tid] = acc;
    __syncthreads();
    if (tid < 32) {
        float4 s = sh[tid];
        #pragma unroll
        for (int hh = 1; hh < 6; hh++) {
            float4 v = sh[hh * 32 + tid];
            s.x += v.x; s.y += v.y; s.z += v.z; s.w += v.w;
        }
        const float inv6 = 1.f / 6.f;
        float4 r = resm4[(size_t)n * 32 + tid];
        const float4 bm = *(const float4*)(b2m + tid * 4);
        s.x = s.x * inv6 + r.x + bm.x;
        s.y = s.y * inv6 + r.y + bm.y;
        s.z = s.z * inv6 + r.z + bm.z;
        s.w = s.w * inv6 + r.w + bm.w;
        local4[(size_t)n * 32 + tid] = s;
        int g = gid[n];
        float* gs = gsum + g * DIM + tid * 4;
        atomicAdd(gs + 0, s.x); atomicAdd(gs + 1, s.y);
        atomicAdd(gs + 2, s.z); atomicAdd(gs + 3, s.w);
        if (tid == 0) atomicAdd(&gcnt[g], 1);
    }
}

__global__ void k_global_fc(const float* __restrict__ gsum, const int* __restrict__ gcnt,
                            const float* __restrict__ Wm, const float* __restrict__ bm,
                            float* __restrict__ out) {
    int g = blockIdx.x;
    int m = threadIdx.x;
    __shared__ float p[DIM];
    float c = fmaxf((float)gcnt[g], 1.f);
    p[m] = gsum[g * DIM + m] / c;
    __syncthreads();
    float acc = bm[m];
    #pragma unroll
    for (int d = 0; d < DIM; d++) acc += p[d] * Wm[d * DIM + m];
    out[(size_t)g * DIM + m] = acc;
}

// ---------------- launch ----------------------------------------------------
extern "C" void kernel_launch(void* const* d_in, const int* in_sizes, int n_in,
                              void* d_out, int out_size) {
    const float* h    = (const float*)d_in[0];
    const int*   src  = (const int*)d_in[2];
    const int*   dst  = (const int*)d_in[3];
    const int*   gid  = (const int*)d_in[4];
    const float* W0   = (const float*)d_in[5];
    const float* al0  = (const float*)d_in[6];
    const float* ar0  = (const float*)d_in[7];
    const float* b0   = (const float*)d_in[8];
    const float* W1   = (const float*)d_in[9];
    const float* al1  = (const float*)d_in[10];
    const float* ar1  = (const float*)d_in[11];
    const float* b1   = (const float*)d_in[12];
    const float* W2   = (const float*)d_in[13];
    const float* al2  = (const float*)d_in[14];
    const float* ar2  = (const float*)d_in[15];
    const float* b2   = (const float*)d_in[16];
    const float* resW2= (const float*)d_in[17];
    const float* Wm   = (const float*)d_in[18];
    const float* bm   = (const float*)d_in[19];
    float* out = (float*)d_out;

    void *pfeat, *px1, *px2, *pres, *pel, *per, *palpha, *pcounts, *poff,
         *pcursor, *pssrc, *pgsum, *pgcnt, *pb2m, *ph16, *px1h, *px2h, *pwt;
    cudaGetSymbolAddress(&pfeat, g_feat);
    cudaGetSymbolAddress(&px1, g_x1);
    cudaGetSymbolAddress(&px2, g_x2);
    cudaGetSymbolAddress(&pres, g_res);
    cudaGetSymbolAddress(&pel, g_el);
    cudaGetSymbolAddress(&per, g_er);
    cudaGetSymbolAddress(&palpha, g_alpha);
    cudaGetSymbolAddress(&pcounts, g_counts);
    cudaGetSymbolAddress(&poff, g_off);
    cudaGetSymbolAddress(&pcursor, g_cursor);
    cudaGetSymbolAddress(&pssrc, g_ssrc);
    cudaGetSymbolAddress(&pgsum, g_gsum);
    cudaGetSymbolAddress(&pgcnt, g_gcnt);
    cudaGetSymbolAddress(&pb2m, g_b2m);
    cudaGetSymbolAddress(&ph16, g_h16);
    cudaGetSymbolAddress(&px1h, g_x1h);
    cudaGetSymbolAddress(&px2h, g_x2h);
    cudaGetSymbolAddress(&pwt, g_wt16);
    __half* feat16 = (__half*)pfeat;
    float* x1 = (float*)px1;
    float* x2 = (float*)px2;
    float* resm = (float*)pres;
    float* el = (float*)pel;
    float* er = (float*)per;
    float* alpha = (float*)palpha;
    int* counts = (int*)pcounts;
    int* off = (int*)poff;
    int* cursor = (int*)pcursor;
    int* ssrc = (int*)pssrc;
    float* gsum = (float*)pgsum;
    int* gcnt = (int*)pgcnt;
    float* b2m = (float*)pb2m;
    __half* h16 = (__half*)ph16;
    __half* x1h = (__half*)px1h;
    __half* x2h = (__half*)px2h;
    __half* wt = (__half*)pwt;

    __half* W0t = wt;                 // [512][128]
    __half* W1t = wt + 65536;         // [512][512]
    __half* W2t = wt + 327680;        // [768][512]
    __half* rW2mt = wt + 720896;      // [128][512]

    const int N = N_NODES, E = N_EDGES;
    dim3 gemmBlk(256);
    dim3 tblk(32, 8);
    int gy = (N + GBM - 1) / GBM;

    // ---- prep + CSR build (L0 GEMM in the ncu-profiled slot) ----
    k_zero_int<<<(N + 255) / 256, 256>>>(counts, N);
    k_f2h<<<(N * 128 / 4 + 255) / 256, 256>>>((const float4*)h, h16, N * 128 / 4);
    k_w2h_t<<<dim3(512 / 32, 128 / 32), tblk>>>(W0, W0t, 128, 512);
    k_h16gemm<<<dim3(4, gy), gemmBlk, GEMM_SMEM>>>(h16, W0t, nullptr, feat16, N, 128, 512);
    k_count<<<(E + 255) / 256, 256>>>(dst, counts, E);
    k_scan<<<1, 1024>>>(counts, off, cursor, N);
    k_fill<<<(E + 255) / 256, 256>>>(dst, src, cursor, ssrc, E);
    k_w2h_t<<<dim3(512 / 32, 512 / 32), tblk>>>(W1, W1t, 512, 512);
    k_w2h_t<<<dim3(768 / 32, 512 / 32), tblk>>>(W2, W2t, 512, 768);
    k_wmean_t<<<(128 * 512 + 255) / 256, 256>>>(resW2, rW2mt);
    k_b2m<<<1, 128>>>(b2, b2m);
    k_zero_float<<<(N_GRAPHS * DIM + 255) / 256, 256>>>(gsum, N_GRAPHS * DIM);
    k_zero_int<<<1, 64>>>(gcnt, N_GRAPHS);

    // ---- layer 0: H=4, no residual, elu ----
    {
        int warps = N * 4;
        k_logits<<<(warps * 32 + 255) / 256, 256>>>((const uint2*)feat16,
            (const float4*)al0, (const float4*)ar0, el, er, 4);
        k_alpha<<<(N * 4 + 255) / 256, 256>>>(el, er, ssrc, off, alpha, 4);
        k_aggregate<<<N, 128>>>((const uint2*)feat16, ssrc, off, alpha,
            nullptr, (const float4*)b0, (float4*)x1, x1h, 4, 1);
    }
    // ---- layer 1: H=4, identity residual, elu ----
    {
        k_h16gemm<<<dim3(4, gy), gemmBlk, GEMM_SMEM>>>(x1h, W1t, nullptr, feat16, N, 512, 512);
        int warps = N * 4;
        k_logits<<<(warps * 32 + 255) / 256, 256>>>((const uint2*)feat16,
            (const float4*)al1, (const float4*)ar1, el, er, 4);
        k_alpha<<<(N * 4 + 255) / 256, 256>>>(el, er, ssrc, off, alpha, 4);
        k_aggregate<<<N, 128>>>((const uint2*)feat16, ssrc, off, alpha,
            (const float4*)x1, (const float4*)b1, (float4*)x2, x2h, 4, 1);
    }
    // ---- layer 2: H=6, mean-residual via small GEMM, fused pool ----
    {
        k_h16gemm<<<dim3(6, gy), gemmBlk, GEMM_SMEM>>>(x2h, W2t, nullptr, feat16, N, 512, 768);
        k_h16gemm<<<dim3(1, gy), gemmBlk, GEMM_SMEM>>>(x2h, rW2mt, resm, nullptr, N, 512, 128);
        int warps = N * 6;
        k_logits<<<(warps * 32 + 255) / 256, 256>>>((const uint2*)feat16,
            (const float4*)al2, (const float4*)ar2, el, er, 6);
        k_alpha<<<(N * 6 + 255) / 256, 256>>>(el, er, ssrc, off, alpha, 6);
        k_agg2_pool<<<N, 192>>>((const uint2*)feat16, ssrc, off, alpha,
            (const float4*)resm, b2m, gid, (float4*)out, gsum, gcnt);
    }
    k_global_fc<<<N_GRAPHS, DIM>>>(gsum, gcnt, Wm, bm, out + (size_t)N * DIM);
}